// round 1
// baseline (speedup 1.0000x reference)
#include <cuda_runtime.h>
#include <cstdint>

// ---------------------------------------------------------------------------
// RGCNEncoder: B=128, R=6, N=256, D_IN=2048, D_H=512
//
//  x0 = relu(attn @ W_embed + b_embed)                    (32768 x 512)
//  layer l:  Y[b,r] = x[b] @ W_rel_l[r]  (r=0..5), Y[b,6] = x[b] @ W_loop_l
//            msgs[b] = sum_r E[b,r] @ Y[b,r] + Y[b,6] + b_l ; relu
//
// Implemented as 3 tiled fp32 SGEMM kernels (128x128x16 blocks, 8x8/thread).
// ---------------------------------------------------------------------------

#define BM 128
#define BN 128
#define BK 16
#define TM 8
#define TN 8
// 256 threads per block: 16x16 thread grid of 8x8 tiles

static __device__ float g_X0[32768u * 512u];                 // 67 MB
static __device__ float g_X1[32768u * 512u];                 // 67 MB
static __device__ float g_Z[128u * 7u * 256u * 512u];        // 470 MB scratch

// ---- shared tile loaders ---------------------------------------------------

// Load a BM x BK tile of A (row-major, row stride lda) into As transposed:
// As[k][m]. Abase points at (row0, k0) of the tile.
__device__ __forceinline__ void load_A_tile(const float* __restrict__ Abase,
                                            int lda, float (*As)[BM], int tid) {
    int a_row = tid >> 2;            // 0..63
    int a_c4  = (tid & 3) << 2;      // 0,4,8,12
#pragma unroll
    for (int t = 0; t < 2; t++) {
        int r = a_row + t * 64;
        float4 v = *(const float4*)(Abase + (size_t)r * lda + a_c4);
        As[a_c4 + 0][r] = v.x;
        As[a_c4 + 1][r] = v.y;
        As[a_c4 + 2][r] = v.z;
        As[a_c4 + 3][r] = v.w;
    }
}

// Load a BK x BN tile of B (row-major, row stride ldb) into Bs[k][n].
__device__ __forceinline__ void load_B_tile(const float* __restrict__ Bbase,
                                            int ldb, float (*Bs)[BN], int tid) {
    int b_row = tid >> 5;            // 0..7
    int b_c4  = (tid & 31) << 2;     // 0..124
#pragma unroll
    for (int t = 0; t < 2; t++) {
        int r = b_row + t * 8;
        *(float4*)&Bs[r][b_c4] = *(const float4*)(Bbase + (size_t)r * ldb + b_c4);
    }
}

__device__ __forceinline__ void mma_tile(const float (*As)[BM],
                                         const float (*Bs)[BN],
                                         float acc[TM][TN], int trow, int tcol) {
#pragma unroll
    for (int kk = 0; kk < BK; kk++) {
        float ra[TM], rb[TN];
#pragma unroll
        for (int i = 0; i < TM; i++) ra[i] = As[kk][trow * TM + i];
#pragma unroll
        for (int j = 0; j < TN; j++) rb[j] = Bs[kk][tcol * TN + j];
#pragma unroll
        for (int i = 0; i < TM; i++)
#pragma unroll
            for (int j = 0; j < TN; j++)
                acc[i][j] = fmaf(ra[i], rb[j], acc[i][j]);
    }
}

// ---- kernel 1: embed  C = relu(A @ W + bias) ------------------------------
// A: (32768 x 2048), W: (2048 x 512), C: (32768 x 512)
__global__ void __launch_bounds__(256) gemm_embed(const float* __restrict__ A,
                                                  const float* __restrict__ W,
                                                  const float* __restrict__ bias,
                                                  float* __restrict__ C) {
    const int K = 2048, NC = 512;
    __shared__ float As[BK][BM];
    __shared__ float Bs[BK][BN];
    int bx = blockIdx.x, by = blockIdx.y;
    int tid = threadIdx.x;
    int tcol = tid & 15, trow = tid >> 4;

    float acc[TM][TN];
#pragma unroll
    for (int i = 0; i < TM; i++)
#pragma unroll
        for (int j = 0; j < TN; j++) acc[i][j] = 0.f;

    const float* Ab = A + (size_t)by * BM * K;
    const float* Wb = W + bx * BN;

    for (int k0 = 0; k0 < K; k0 += BK) {
        load_A_tile(Ab + k0, K, As, tid);
        load_B_tile(Wb + (size_t)k0 * NC, NC, Bs, tid);
        __syncthreads();
        mma_tile(As, Bs, acc, trow, tcol);
        __syncthreads();
    }

#pragma unroll
    for (int i = 0; i < TM; i++) {
        int row = by * BM + trow * TM + i;
#pragma unroll
        for (int j = 0; j < TN; j++) {
            int col = bx * BN + tcol * TN + j;
            float v = acc[i][j] + bias[col];
            C[(size_t)row * NC + col] = fmaxf(v, 0.f);
        }
    }
}

// ---- kernel 2: expand  Z[b,r,n,:] = X[b,n,:] @ W_r  (r=0..5: W_rel, r=6: W_loop)
// X: (32768 x 512) row-major; Z: (B,7,N,512)
__global__ void __launch_bounds__(256) gemm_expand(const float* __restrict__ X,
                                                   const float* __restrict__ W_rel,
                                                   const float* __restrict__ W_loop,
                                                   float* __restrict__ Z) {
    const int K = 512;
    __shared__ float As[BK][BM];
    __shared__ float Bs[BK][BN];
    int bx = blockIdx.x;              // 0..27 -> r = bx/4, col block within r
    int by = blockIdx.y;              // 0..255
    int tid = threadIdx.x;
    int tcol = tid & 15, trow = tid >> 4;

    int r  = bx >> 2;
    int d0 = (bx & 3) * BN;
    const float* Wb = (r < 6 ? W_rel + (size_t)r * 512 * 512 : W_loop) + d0;
    const float* Ab = X + (size_t)by * BM * K;

    float acc[TM][TN];
#pragma unroll
    for (int i = 0; i < TM; i++)
#pragma unroll
        for (int j = 0; j < TN; j++) acc[i][j] = 0.f;

    for (int k0 = 0; k0 < K; k0 += BK) {
        load_A_tile(Ab + k0, K, As, tid);
        load_B_tile(Wb + (size_t)k0 * 512, 512, Bs, tid);
        __syncthreads();
        mma_tile(As, Bs, acc, trow, tcol);
        __syncthreads();
    }

#pragma unroll
    for (int i = 0; i < TM; i++) {
        int m  = by * BM + trow * TM + i;   // global row = b*256 + n
        int b  = m >> 8;
        int nn = m & 255;
        size_t base = ((size_t)b * 7 + r) * (256u * 512u) + (size_t)nn * 512u;
#pragma unroll
        for (int j = 0; j < TN; j++) {
            int d = d0 + tcol * TN + j;
            Z[base + d] = acc[i][j];
        }
    }
}

// ---- kernel 3: aggregate
// out[b,i,d] = relu( sum_{r<6,j} E[b,r,i,j] * Z[b,r,j,d] + Z[b,6,i,d] + bias[d] )
// Batched over b (blockIdx.z). K = 6*256 = 1536.
__global__ void __launch_bounds__(256) gemm_agg(const float* __restrict__ E,
                                                const float* __restrict__ Z,
                                                const float* __restrict__ bias,
                                                float* __restrict__ Out) {
    __shared__ float As[BK][BM];
    __shared__ float Bs[BK][BN];
    int b  = blockIdx.z;
    int bx = blockIdx.x;              // 0..3   (512/128)
    int by = blockIdx.y;              // 0..1   (256/128)
    int tid = threadIdx.x;
    int tcol = tid & 15, trow = tid >> 4;

    const float* Eb = E + (size_t)b * 6u * 256u * 256u;
    const float* Zb = Z + (size_t)b * 7u * 256u * 512u;

    float acc[TM][TN];
#pragma unroll
    for (int i = 0; i < TM; i++)
#pragma unroll
        for (int j = 0; j < TN; j++) acc[i][j] = 0.f;

    for (int k0 = 0; k0 < 1536; k0 += BK) {
        int r  = k0 >> 8;             // relation index
        int j0 = k0 & 255;            // column within E[b,r], row within Z[b,r]
        // A tile: E[b, r, by*128 + i, j0 + kk], row stride 256
        const float* Abase = Eb + (size_t)r * 65536u + (size_t)(by * BM) * 256u + j0;
        // B tile: Z[b, r, j0 + kk, bx*128 + d], row stride 512
        const float* Bbase = Zb + (size_t)r * 131072u + (size_t)j0 * 512u + bx * BN;
        load_A_tile(Abase, 256, As, tid);
        load_B_tile(Bbase, 512, Bs, tid);
        __syncthreads();
        mma_tile(As, Bs, acc, trow, tcol);
        __syncthreads();
    }

    const float* Zloop = Zb + 6u * 131072u;   // self-loop slice Z[b,6,:,:]
#pragma unroll
    for (int i = 0; i < TM; i++) {
        int row = by * BM + trow * TM + i;    // node index i within batch b
#pragma unroll
        for (int j = 0; j < TN; j++) {
            int col = bx * BN + tcol * TN + j;
            float v = acc[i][j] + Zloop[(size_t)row * 512u + col] + bias[col];
            Out[(size_t)b * 131072u + (size_t)row * 512u + col] = fmaxf(v, 0.f);
        }
    }
}

// ---------------------------------------------------------------------------

extern "C" void kernel_launch(void* const* d_in, const int* in_sizes, int n_in,
                              void* d_out, int out_size) {
    const float* attn = (const float*)d_in[0];   // (128,256,2048)
    const float* E    = (const float*)d_in[1];   // (128,6,256,256)
    const float* Wemb = (const float*)d_in[2];   // (2048,512)
    const float* bemb = (const float*)d_in[3];   // (512,)
    const float* Wr0  = (const float*)d_in[4];   // (6,512,512)
    const float* Wl0  = (const float*)d_in[5];   // (512,512)
    const float* b0   = (const float*)d_in[6];   // (512,)
    const float* Wr1  = (const float*)d_in[7];
    const float* Wl1  = (const float*)d_in[8];
    const float* b1   = (const float*)d_in[9];
    float* out = (float*)d_out;                  // (128,256,512)

    float *X0, *X1, *Z;
    cudaGetSymbolAddress((void**)&X0, g_X0);
    cudaGetSymbolAddress((void**)&X1, g_X1);
    cudaGetSymbolAddress((void**)&Z,  g_Z);

    // embed
    gemm_embed<<<dim3(4, 256), 256>>>(attn, Wemb, bemb, X0);
    // layer 0
    gemm_expand<<<dim3(28, 256), 256>>>(X0, Wr0, Wl0, Z);
    gemm_agg<<<dim3(4, 2, 128), 256>>>(E, Z, b0, X1);
    // layer 1
    gemm_expand<<<dim3(28, 256), 256>>>(X1, Wr1, Wl1, Z);
    gemm_agg<<<dim3(4, 2, 128), 256>>>(E, Z, b1, out);
}

// round 3
// speedup vs baseline: 3.5085x; 3.5085x over previous
#include <cuda_runtime.h>
#include <cstdint>

// ---------------------------------------------------------------------------
// RGCNEncoder via mma.sync tf32 tensor cores (family-target safe, no tcgen05).
// B=128, R=6, N=256, D_IN=2048, D_H=512
//
//   x0 = relu(attn @ W_embed + b_embed)
//   layer l: Z[b,r] = x[b] @ W_rel_l[r] (r<6), Z[b,6] = x[b] @ W_loop_l
//            out[b] = relu(sum_r E[b,r] @ Z[b,r] + Z[b,6] + bias)
//
// All GEMMs: CTA tile 128x128, K-chunk 32, 8 warps x (64x32) warp tiles,
// m16n8k8 tf32 fragments, cp.async double buffer, fp32 accumulate.
// A row-major (k contiguous), B row-major (k x n) -- no transposes needed.
// ---------------------------------------------------------------------------

static __device__ float g_X0[32768u * 512u];
static __device__ float g_X1[32768u * 512u];
static __device__ float g_Z[128u * 7u * 256u * 512u];   // [b][r][n][d]

#define BM 128
#define BN 128
#define BK 32
#define ASTR 36     // BK + 4 pad (floats)
#define BSTR 132    // BN + 4 pad (floats)

static constexpr int AS_FLOATS = BM * ASTR;           // one A buffer
static constexpr int BS_FLOATS = BK * BSTR;           // one B buffer
static constexpr int SMEM_BYTES = (2 * AS_FLOATS + 2 * BS_FLOATS) * 4;  // 70656

// ---- low-level helpers -----------------------------------------------------

__device__ __forceinline__ uint32_t smem_u32(const void* p) {
    uint32_t a;
    asm("{ .reg .u64 t; cvta.to.shared.u64 t, %1; cvt.u32.u64 %0, t; }"
        : "=r"(a) : "l"(p));
    return a;
}
__device__ __forceinline__ void cp_async16(uint32_t dst, const void* src) {
    asm volatile("cp.async.cg.shared.global [%0], [%1], 16;" ::"r"(dst), "l"(src));
}
__device__ __forceinline__ void cp_commit() {
    asm volatile("cp.async.commit_group;" ::: "memory");
}
template <int N>
__device__ __forceinline__ void cp_wait() {
    asm volatile("cp.async.wait_group %0;" ::"n"(N) : "memory");
}
__device__ __forceinline__ uint32_t f2tf(float x) {
    uint32_t r;
    asm("cvt.rna.tf32.f32 %0, %1;" : "=r"(r) : "f"(x));
    return r;
}
__device__ __forceinline__ void mma8(float* c, const uint32_t* a, const uint32_t* b) {
    asm volatile(
        "mma.sync.aligned.m16n8k8.row.col.f32.tf32.tf32.f32 "
        "{%0,%1,%2,%3}, {%4,%5,%6,%7}, {%8,%9}, {%0,%1,%2,%3};"
        : "+f"(c[0]), "+f"(c[1]), "+f"(c[2]), "+f"(c[3])
        : "r"(a[0]), "r"(a[1]), "r"(a[2]), "r"(a[3]), "r"(b[0]), "r"(b[1]));
}

// 128x32 float tile (row-major, stride lda) -> padded smem, 256 threads
__device__ __forceinline__ void ld_tileA(uint32_t dst, const float* __restrict__ src,
                                         int lda, int tid) {
#pragma unroll
    for (int i = 0; i < 4; i++) {
        int idx = tid + i * 256;
        int row = idx >> 3, seg = idx & 7;
        cp_async16(dst + (uint32_t)(row * ASTR + seg * 4) * 4,
                   src + (size_t)row * lda + seg * 4);
    }
}
// 32x128 float tile (row-major, stride ldb) -> padded smem, 256 threads
__device__ __forceinline__ void ld_tileB(uint32_t dst, const float* __restrict__ src,
                                         int ldb, int tid) {
#pragma unroll
    for (int i = 0; i < 4; i++) {
        int idx = tid + i * 256;
        int row = idx >> 5, seg = idx & 31;
        cp_async16(dst + (uint32_t)(row * BSTR + seg * 4) * 4,
                   src + (size_t)row * ldb + seg * 4);
    }
}

// ---- shared mainloop -------------------------------------------------------

template <class F>
__device__ __forceinline__ void gemm_main(const F& f, int nc, float* sm,
                                          float acc[4][4][4]) {
    const int tid = threadIdx.x;
    const uint32_t sbase = smem_u32(sm);
    const int aF[2] = {0, AS_FLOATS};
    const int bF[2] = {2 * AS_FLOATS, 2 * AS_FLOATS + BS_FLOATS};

    ld_tileA(sbase + (uint32_t)aF[0] * 4, f.a(0), f.lda, tid);
    ld_tileB(sbase + (uint32_t)bF[0] * 4, f.b(0), f.ldb, tid);
    cp_commit();
    ld_tileA(sbase + (uint32_t)aF[1] * 4, f.a(1), f.lda, tid);
    ld_tileB(sbase + (uint32_t)bF[1] * 4, f.b(1), f.ldb, tid);
    cp_commit();

    const int lane = tid & 31, wid = tid >> 5;
    const int gid = lane >> 2, tig = lane & 3;
    const int wm = (wid >> 2) * 64, wn = (wid & 3) * 32;

    for (int c = 0; c < nc; c++) {
        if (c + 1 < nc) cp_wait<1>(); else cp_wait<0>();
        __syncthreads();
        const int ao = aF[c & 1], bo = bF[c & 1];
#pragma unroll
        for (int kk = 0; kk < BK; kk += 8) {
            uint32_t a[4][4], b[4][2];
#pragma unroll
            for (int mt = 0; mt < 4; mt++) {
                int r0 = ao + (wm + mt * 16 + gid) * ASTR + kk + tig;
                a[mt][0] = f2tf(sm[r0]);
                a[mt][1] = f2tf(sm[r0 + 8 * ASTR]);
                a[mt][2] = f2tf(sm[r0 + 4]);
                a[mt][3] = f2tf(sm[r0 + 8 * ASTR + 4]);
            }
#pragma unroll
            for (int nt = 0; nt < 4; nt++) {
                int c0 = bo + (kk + tig) * BSTR + wn + nt * 8 + gid;
                b[nt][0] = f2tf(sm[c0]);
                b[nt][1] = f2tf(sm[c0 + 4 * BSTR]);
            }
#pragma unroll
            for (int mt = 0; mt < 4; mt++)
#pragma unroll
                for (int nt = 0; nt < 4; nt++) mma8(acc[mt][nt], a[mt], b[nt]);
        }
        __syncthreads();
        if (c + 2 < nc) {
            ld_tileA(sbase + (uint32_t)aF[c & 1] * 4, f.a(c + 2), f.lda, tid);
            ld_tileB(sbase + (uint32_t)bF[c & 1] * 4, f.b(c + 2), f.ldb, tid);
            cp_commit();
        }
    }
}

// ---- address functors ------------------------------------------------------

struct LinAddr {
    const float *A, *B;
    int lda, ldb;
    __device__ const float* a(int c) const { return A + c * BK; }
    __device__ const float* b(int c) const { return B + (size_t)c * BK * ldb; }
};
struct AggAddr {
    const float *Eb, *Zb;  // Eb: E[b] + row offset; Zb: Z[b] + col offset
    int lda, ldb;
    __device__ const float* a(int c) const {
        return Eb + (size_t)(c >> 3) * 65536u + (c & 7) * BK;
    }
    __device__ const float* b(int c) const {
        return Zb + (size_t)(c >> 3) * 131072u + (size_t)(c & 7) * BK * 512;
    }
};

// ---- kernels ---------------------------------------------------------------

__global__ void __launch_bounds__(256) k_embed(const float* __restrict__ attn,
                                               const float* __restrict__ W,
                                               const float* __restrict__ bias,
                                               float* __restrict__ out) {
    extern __shared__ float sm[];
    const int bx = blockIdx.x, by = blockIdx.y;
    float acc[4][4][4];
#pragma unroll
    for (int i = 0; i < 4; i++)
#pragma unroll
        for (int j = 0; j < 4; j++)
#pragma unroll
            for (int k = 0; k < 4; k++) acc[i][j][k] = 0.f;

    LinAddr f{attn + (size_t)by * 128 * 2048, W + bx * 128, 2048, 512};
    gemm_main(f, 64, sm, acc);

    const int tid = threadIdx.x, lane = tid & 31, wid = tid >> 5;
    const int gid = lane >> 2, tig = lane & 3;
    const int wm = (wid >> 2) * 64, wn = (wid & 3) * 32;
#pragma unroll
    for (int mt = 0; mt < 4; mt++) {
        int row = by * 128 + wm + mt * 16 + gid;
#pragma unroll
        for (int nt = 0; nt < 4; nt++) {
            int col = bx * 128 + wn + nt * 8 + tig * 2;
            float b0 = bias[col], b1 = bias[col + 1];
            float2 v0 = make_float2(fmaxf(acc[mt][nt][0] + b0, 0.f),
                                    fmaxf(acc[mt][nt][1] + b1, 0.f));
            float2 v1 = make_float2(fmaxf(acc[mt][nt][2] + b0, 0.f),
                                    fmaxf(acc[mt][nt][3] + b1, 0.f));
            *(float2*)&out[(size_t)row * 512 + col] = v0;
            *(float2*)&out[(size_t)(row + 8) * 512 + col] = v1;
        }
    }
}

__global__ void __launch_bounds__(256) k_expand(const float* __restrict__ X,
                                                const float* __restrict__ Wrel,
                                                const float* __restrict__ Wloop,
                                                float* __restrict__ Z) {
    extern __shared__ float sm[];
    const int bx = blockIdx.x, by = blockIdx.y;
    const int r = bx >> 2, d0 = (bx & 3) * 128;
    float acc[4][4][4];
#pragma unroll
    for (int i = 0; i < 4; i++)
#pragma unroll
        for (int j = 0; j < 4; j++)
#pragma unroll
            for (int k = 0; k < 4; k++) acc[i][j][k] = 0.f;

    const float* Bp = (r < 6 ? Wrel + (size_t)r * 262144u : Wloop) + d0;
    LinAddr f{X + (size_t)by * 128 * 512, Bp, 512, 512};
    gemm_main(f, 16, sm, acc);

    const int tid = threadIdx.x, lane = tid & 31, wid = tid >> 5;
    const int gid = lane >> 2, tig = lane & 3;
    const int wm = (wid >> 2) * 64, wn = (wid & 3) * 32;
#pragma unroll
    for (int mt = 0; mt < 4; mt++) {
        int m = by * 128 + wm + mt * 16 + gid;
        int b = m >> 8, n = m & 255;
        size_t zb = ((size_t)b * 7 + r) * 256u;
#pragma unroll
        for (int nt = 0; nt < 4; nt++) {
            int d = d0 + wn + nt * 8 + tig * 2;
            *(float2*)&Z[(zb + n) * 512u + d] =
                make_float2(acc[mt][nt][0], acc[mt][nt][1]);
            *(float2*)&Z[(zb + n + 8) * 512u + d] =
                make_float2(acc[mt][nt][2], acc[mt][nt][3]);
        }
    }
}

__global__ void __launch_bounds__(256) k_agg(const float* __restrict__ E,
                                             const float* __restrict__ Z,
                                             const float* __restrict__ bias,
                                             float* __restrict__ out) {
    extern __shared__ float sm[];
    const int bx = blockIdx.x, by = blockIdx.y, b = blockIdx.z;
    float acc[4][4][4];
#pragma unroll
    for (int i = 0; i < 4; i++)
#pragma unroll
        for (int j = 0; j < 4; j++)
#pragma unroll
            for (int k = 0; k < 4; k++) acc[i][j][k] = 0.f;

    AggAddr f{E + (size_t)b * 393216u + (size_t)(by * 128) * 256u,
              Z + (size_t)b * 917504u + bx * 128, 256, 512};
    gemm_main(f, 48, sm, acc);

    const float* Zl = Z + (size_t)b * 917504u + 6u * 131072u;
    const int tid = threadIdx.x, lane = tid & 31, wid = tid >> 5;
    const int gid = lane >> 2, tig = lane & 3;
    const int wm = (wid >> 2) * 64, wn = (wid & 3) * 32;
#pragma unroll
    for (int mt = 0; mt < 4; mt++) {
        int i = by * 128 + wm + mt * 16 + gid;
#pragma unroll
        for (int nt = 0; nt < 4; nt++) {
            int d = bx * 128 + wn + nt * 8 + tig * 2;
            float b0 = bias[d], b1 = bias[d + 1];
            float2 l0 = *(const float2*)&Zl[(size_t)i * 512 + d];
            float2 l1 = *(const float2*)&Zl[(size_t)(i + 8) * 512 + d];
            float2 v0 = make_float2(fmaxf(acc[mt][nt][0] + l0.x + b0, 0.f),
                                    fmaxf(acc[mt][nt][1] + l0.y + b1, 0.f));
            float2 v1 = make_float2(fmaxf(acc[mt][nt][2] + l1.x + b0, 0.f),
                                    fmaxf(acc[mt][nt][3] + l1.y + b1, 0.f));
            *(float2*)&out[((size_t)b * 256 + i) * 512 + d] = v0;
            *(float2*)&out[((size_t)b * 256 + i + 8) * 512 + d] = v1;
        }
    }
}

// ---------------------------------------------------------------------------

extern "C" void kernel_launch(void* const* d_in, const int* in_sizes, int n_in,
                              void* d_out, int out_size) {
    const float* attn = (const float*)d_in[0];
    const float* E    = (const float*)d_in[1];
    const float* Wemb = (const float*)d_in[2];
    const float* bemb = (const float*)d_in[3];
    const float* Wr0  = (const float*)d_in[4];
    const float* Wl0  = (const float*)d_in[5];
    const float* b0   = (const float*)d_in[6];
    const float* Wr1  = (const float*)d_in[7];
    const float* Wl1  = (const float*)d_in[8];
    const float* b1   = (const float*)d_in[9];
    float* out = (float*)d_out;

    float *X0, *X1, *Z;
    cudaGetSymbolAddress((void**)&X0, g_X0);
    cudaGetSymbolAddress((void**)&X1, g_X1);
    cudaGetSymbolAddress((void**)&Z, g_Z);

    cudaFuncSetAttribute(k_embed, cudaFuncAttributeMaxDynamicSharedMemorySize, SMEM_BYTES);
    cudaFuncSetAttribute(k_expand, cudaFuncAttributeMaxDynamicSharedMemorySize, SMEM_BYTES);
    cudaFuncSetAttribute(k_agg, cudaFuncAttributeMaxDynamicSharedMemorySize, SMEM_BYTES);

    k_embed<<<dim3(4, 256), 256, SMEM_BYTES>>>(attn, Wemb, bemb, X0);

    k_expand<<<dim3(28, 256), 256, SMEM_BYTES>>>(X0, Wr0, Wl0, Z);
    k_agg<<<dim3(4, 2, 128), 256, SMEM_BYTES>>>(E, Z, b0, X1);

    k_expand<<<dim3(28, 256), 256, SMEM_BYTES>>>(X1, Wr1, Wl1, Z);
    k_agg<<<dim3(4, 2, 128), 256, SMEM_BYTES>>>(E, Z, b1, out);
}

// round 4
// speedup vs baseline: 3.7617x; 1.0722x over previous
#include <cuda_runtime.h>
#include <cstdint>

// ---------------------------------------------------------------------------
// RGCNEncoder via mma.sync tf32 tensor cores.
// B=128, R=6, N=256, D_IN=2048, D_H=512
//
// All GEMMs: CTA tile 128x128, K-chunk 32, 8 warps x (64x32) warp tiles,
// m16n8k8 tf32, 3-stage cp.async pipeline, fp32 accumulate.
// All internally-produced operands (X0, X1, Z, weights) are stored already
// rounded to tf32, so their mainloop loads need no cvt. Only the external
// A operands (attn, rel_edges) are cvt.rna'd in-loop.
// ---------------------------------------------------------------------------

static __device__ float g_X0[32768u * 512u];
static __device__ float g_X1[32768u * 512u];
static __device__ float g_Z[128u * 7u * 256u * 512u];   // [b][r][n][d]
static __device__ float g_WembR[2048u * 512u];          // rounded W_embed
static __device__ float g_WR[2u][7u * 512u * 512u];     // rounded [r<6]=rel, [6]=loop

#define BM 128
#define BN 128
#define BK 32
#define ASTR 36     // BK + 4 pad   (4*gid+tig -> conflict-free frag loads)
#define BSTR 136    // BN + 8 pad   (8*tig+gid -> conflict-free frag loads)

static constexpr int AS_FLOATS = BM * ASTR;                    // 4608
static constexpr int BS_FLOATS = BK * BSTR;                    // 4352
static constexpr int STAGE_F   = AS_FLOATS + BS_FLOATS;        // 8960
static constexpr uint32_t AS_BYTES  = AS_FLOATS * 4;           // 18432
static constexpr uint32_t STAGE_B   = STAGE_F * 4;             // 35840
static constexpr int SMEM_BYTES = 3 * STAGE_B;                 // 107520

// ---- low-level helpers -----------------------------------------------------

__device__ __forceinline__ uint32_t smem_u32(const void* p) {
    uint32_t a;
    asm("{ .reg .u64 t; cvta.to.shared.u64 t, %1; cvt.u32.u64 %0, t; }"
        : "=r"(a) : "l"(p));
    return a;
}
__device__ __forceinline__ void cp_async16(uint32_t dst, const void* src) {
    asm volatile("cp.async.cg.shared.global [%0], [%1], 16;" ::"r"(dst), "l"(src));
}
__device__ __forceinline__ void cp_commit() {
    asm volatile("cp.async.commit_group;" ::: "memory");
}
template <int N>
__device__ __forceinline__ void cp_wait() {
    asm volatile("cp.async.wait_group %0;" ::"n"(N) : "memory");
}
__device__ __forceinline__ uint32_t f2tf(float x) {
    uint32_t r;
    asm("cvt.rna.tf32.f32 %0, %1;" : "=r"(r) : "f"(x));
    return r;
}
__device__ __forceinline__ float rnd(float x) {            // tf32-rounded fp32
    return __uint_as_float(f2tf(x));
}
__device__ __forceinline__ void mma8(float* c, const uint32_t* a, const uint32_t* b) {
    asm volatile(
        "mma.sync.aligned.m16n8k8.row.col.f32.tf32.tf32.f32 "
        "{%0,%1,%2,%3}, {%4,%5,%6,%7}, {%8,%9}, {%0,%1,%2,%3};"
        : "+f"(c[0]), "+f"(c[1]), "+f"(c[2]), "+f"(c[3])
        : "r"(a[0]), "r"(a[1]), "r"(a[2]), "r"(a[3]), "r"(b[0]), "r"(b[1]));
}

// 128x32 float tile (row-major, stride lda) -> padded smem, 256 threads
__device__ __forceinline__ void ld_tileA(uint32_t dst, const float* __restrict__ src,
                                         int lda, int tid) {
#pragma unroll
    for (int i = 0; i < 4; i++) {
        int idx = tid + i * 256;
        int row = idx >> 3, seg = idx & 7;
        cp_async16(dst + (uint32_t)(row * ASTR + seg * 4) * 4,
                   src + (size_t)row * lda + seg * 4);
    }
}
// 32x128 float tile (row-major, stride ldb) -> padded smem, 256 threads
__device__ __forceinline__ void ld_tileB(uint32_t dst, const float* __restrict__ src,
                                         int ldb, int tid) {
#pragma unroll
    for (int i = 0; i < 4; i++) {
        int idx = tid + i * 256;
        int row = idx >> 5, seg = idx & 31;
        cp_async16(dst + (uint32_t)(row * BSTR + seg * 4) * 4,
                   src + (size_t)row * ldb + seg * 4);
    }
}

// ---- shared mainloop -------------------------------------------------------

template <bool CVT_A, class F>
__device__ __forceinline__ void gemm_main(const F& f, int nc, float* sm,
                                          float acc[4][4][4]) {
    const int tid = threadIdx.x;
    const uint32_t sbase = smem_u32(sm);
    const int lane = tid & 31, wid = tid >> 5;
    const int gid = lane >> 2, tig = lane & 3;
    const int wm = (wid >> 2) * 64, wn = (wid & 3) * 32;
    const int athr = (wm + gid) * ASTR + tig;
    const int bthr = AS_FLOATS + tig * BSTR + wn + gid;

#pragma unroll
    for (int p = 0; p < 3; p++) {
        if (p < nc) {
            ld_tileA(sbase + p * STAGE_B, f.a(p), f.lda, tid);
            ld_tileB(sbase + p * STAGE_B + AS_BYTES, f.b(p), f.ldb, tid);
        }
        cp_commit();
    }

    int stage = 0;
    for (int c = 0; c < nc; c++) {
        cp_wait<2>();
        __syncthreads();
        const float* ap = sm + stage * STAGE_F + athr;
        const float* bp = sm + stage * STAGE_F + bthr;
#pragma unroll
        for (int kk = 0; kk < BK; kk += 8) {
            uint32_t a[4][4], b[4][2];
#pragma unroll
            for (int mt = 0; mt < 4; mt++) {
                const float* p0 = ap + mt * 16 * ASTR + kk;
                if (CVT_A) {
                    a[mt][0] = f2tf(p0[0]);
                    a[mt][1] = f2tf(p0[8 * ASTR]);
                    a[mt][2] = f2tf(p0[4]);
                    a[mt][3] = f2tf(p0[8 * ASTR + 4]);
                } else {
                    a[mt][0] = __float_as_uint(p0[0]);
                    a[mt][1] = __float_as_uint(p0[8 * ASTR]);
                    a[mt][2] = __float_as_uint(p0[4]);
                    a[mt][3] = __float_as_uint(p0[8 * ASTR + 4]);
                }
            }
#pragma unroll
            for (int nt = 0; nt < 4; nt++) {
                const float* q0 = bp + kk * BSTR + nt * 8;
                b[nt][0] = __float_as_uint(q0[0]);
                b[nt][1] = __float_as_uint(q0[4 * BSTR]);
            }
#pragma unroll
            for (int mt = 0; mt < 4; mt++)
#pragma unroll
                for (int nt = 0; nt < 4; nt++) mma8(acc[mt][nt], a[mt], b[nt]);
        }
        __syncthreads();
        if (c + 3 < nc) {
            ld_tileA(sbase + stage * STAGE_B, f.a(c + 3), f.lda, tid);
            ld_tileB(sbase + stage * STAGE_B + AS_BYTES, f.b(c + 3), f.ldb, tid);
        }
        cp_commit();
        stage = (stage == 2) ? 0 : stage + 1;
    }
}

__device__ __forceinline__ void zero_acc(float acc[4][4][4]) {
#pragma unroll
    for (int i = 0; i < 4; i++)
#pragma unroll
        for (int j = 0; j < 4; j++)
#pragma unroll
            for (int k = 0; k < 4; k++) acc[i][j][k] = 0.f;
}

// ---- address functors ------------------------------------------------------

struct LinAddr {
    const float *A, *B;
    int lda, ldb;
    __device__ const float* a(int c) const { return A + c * BK; }
    __device__ const float* b(int c) const { return B + (size_t)c * BK * ldb; }
};
struct AggAddr {
    const float *Eb, *Zb;
    int lda, ldb;
    __device__ const float* a(int c) const {
        return Eb + (size_t)(c >> 3) * 65536u + (c & 7) * BK;
    }
    __device__ const float* b(int c) const {
        return Zb + (size_t)(c >> 3) * 131072u + (size_t)(c & 7) * BK * 512;
    }
};

// ---- kernels ---------------------------------------------------------------

__global__ void __launch_bounds__(256, 2) k_embed(const float* __restrict__ attn,
                                                  const float* __restrict__ W,
                                                  const float* __restrict__ bias,
                                                  float* __restrict__ out) {
    extern __shared__ float sm[];
    const int bx = blockIdx.x, by = blockIdx.y;
    float acc[4][4][4];
    zero_acc(acc);

    LinAddr f{attn + (size_t)by * 128 * 2048, W + bx * 128, 2048, 512};
    gemm_main<true>(f, 64, sm, acc);   // A = external attn -> cvt in loop

    const int tid = threadIdx.x, lane = tid & 31, wid = tid >> 5;
    const int gid = lane >> 2, tig = lane & 3;
    const int wm = (wid >> 2) * 64, wn = (wid & 3) * 32;
#pragma unroll
    for (int mt = 0; mt < 4; mt++) {
        int row = by * 128 + wm + mt * 16 + gid;
#pragma unroll
        for (int nt = 0; nt < 4; nt++) {
            int col = bx * 128 + wn + nt * 8 + tig * 2;
            float b0 = bias[col], b1 = bias[col + 1];
            float2 v0 = make_float2(rnd(fmaxf(acc[mt][nt][0] + b0, 0.f)),
                                    rnd(fmaxf(acc[mt][nt][1] + b1, 0.f)));
            float2 v1 = make_float2(rnd(fmaxf(acc[mt][nt][2] + b0, 0.f)),
                                    rnd(fmaxf(acc[mt][nt][3] + b1, 0.f)));
            *(float2*)&out[(size_t)row * 512 + col] = v0;
            *(float2*)&out[(size_t)(row + 8) * 512 + col] = v1;
        }
    }
}

__global__ void __launch_bounds__(256, 2) k_expand(const float* __restrict__ X,
                                                   const float* __restrict__ WR,
                                                   float* __restrict__ Z) {
    extern __shared__ float sm[];
    const int bx = blockIdx.x, by = blockIdx.y;
    const int r = bx >> 2, d0 = (bx & 3) * 128;
    float acc[4][4][4];
    zero_acc(acc);

    LinAddr f{X + (size_t)by * 128 * 512, WR + (size_t)r * 262144u + d0, 512, 512};
    gemm_main<false>(f, 16, sm, acc);  // both operands pre-rounded -> no cvt

    const int tid = threadIdx.x, lane = tid & 31, wid = tid >> 5;
    const int gid = lane >> 2, tig = lane & 3;
    const int wm = (wid >> 2) * 64, wn = (wid & 3) * 32;
#pragma unroll
    for (int mt = 0; mt < 4; mt++) {
        int m = by * 128 + wm + mt * 16 + gid;
        int b = m >> 8, n = m & 255;
        size_t zb = ((size_t)b * 7 + r) * 256u;
#pragma unroll
        for (int nt = 0; nt < 4; nt++) {
            int d = d0 + wn + nt * 8 + tig * 2;
            *(float2*)&Z[(zb + n) * 512u + d] =
                make_float2(rnd(acc[mt][nt][0]), rnd(acc[mt][nt][1]));
            *(float2*)&Z[(zb + n + 8) * 512u + d] =
                make_float2(rnd(acc[mt][nt][2]), rnd(acc[mt][nt][3]));
        }
    }
}

template <bool ROUND>
__global__ void __launch_bounds__(256, 2) k_agg(const float* __restrict__ E,
                                                const float* __restrict__ Z,
                                                const float* __restrict__ bias,
                                                float* __restrict__ out) {
    extern __shared__ float sm[];
    const int bx = blockIdx.x, by = blockIdx.y, b = blockIdx.z;
    float acc[4][4][4];
    zero_acc(acc);

    AggAddr f{E + (size_t)b * 393216u + (size_t)(by * 128) * 256u,
              Z + (size_t)b * 917504u + bx * 128, 256, 512};
    gemm_main<true>(f, 48, sm, acc);   // A = external rel_edges -> cvt in loop

    const float* Zl = Z + (size_t)b * 917504u + 6u * 131072u;
    const int tid = threadIdx.x, lane = tid & 31, wid = tid >> 5;
    const int gid = lane >> 2, tig = lane & 3;
    const int wm = (wid >> 2) * 64, wn = (wid & 3) * 32;
#pragma unroll
    for (int mt = 0; mt < 4; mt++) {
        int i = by * 128 + wm + mt * 16 + gid;
#pragma unroll
        for (int nt = 0; nt < 4; nt++) {
            int d = bx * 128 + wn + nt * 8 + tig * 2;
            float b0 = bias[d], b1 = bias[d + 1];
            float2 l0 = *(const float2*)&Zl[(size_t)i * 512 + d];
            float2 l1 = *(const float2*)&Zl[(size_t)(i + 8) * 512 + d];
            float r0 = fmaxf(acc[mt][nt][0] + l0.x + b0, 0.f);
            float r1 = fmaxf(acc[mt][nt][1] + l0.y + b1, 0.f);
            float r2 = fmaxf(acc[mt][nt][2] + l1.x + b0, 0.f);
            float r3 = fmaxf(acc[mt][nt][3] + l1.y + b1, 0.f);
            float2 v0, v1;
            if (ROUND) {
                v0 = make_float2(rnd(r0), rnd(r1));
                v1 = make_float2(rnd(r2), rnd(r3));
            } else {
                v0 = make_float2(r0, r1);
                v1 = make_float2(r2, r3);
            }
            *(float2*)&out[((size_t)b * 256 + i) * 512 + d] = v0;
            *(float2*)&out[((size_t)b * 256 + i + 8) * 512 + d] = v1;
        }
    }
}

// elementwise tf32 rounding pass (for weights)
__global__ void k_round(const float* __restrict__ src, float* __restrict__ dst,
                        int n4) {
    int i = blockIdx.x * blockDim.x + threadIdx.x;
    if (i < n4) {
        float4 v = ((const float4*)src)[i];
        v.x = rnd(v.x); v.y = rnd(v.y); v.z = rnd(v.z); v.w = rnd(v.w);
        ((float4*)dst)[i] = v;
    }
}

// ---------------------------------------------------------------------------

extern "C" void kernel_launch(void* const* d_in, const int* in_sizes, int n_in,
                              void* d_out, int out_size) {
    const float* attn = (const float*)d_in[0];
    const float* E    = (const float*)d_in[1];
    const float* Wemb = (const float*)d_in[2];
    const float* bemb = (const float*)d_in[3];
    const float* Wr0  = (const float*)d_in[4];
    const float* Wl0  = (const float*)d_in[5];
    const float* b0   = (const float*)d_in[6];
    const float* Wr1  = (const float*)d_in[7];
    const float* Wl1  = (const float*)d_in[8];
    const float* b1   = (const float*)d_in[9];
    float* out = (float*)d_out;

    float *X0, *X1, *Z, *WembR, *WR;
    cudaGetSymbolAddress((void**)&X0, g_X0);
    cudaGetSymbolAddress((void**)&X1, g_X1);
    cudaGetSymbolAddress((void**)&Z, g_Z);
    cudaGetSymbolAddress((void**)&WembR, g_WembR);
    cudaGetSymbolAddress((void**)&WR, g_WR);
    float* WR0 = WR;
    float* WR1 = WR + 7u * 262144u;

    cudaFuncSetAttribute(k_embed, cudaFuncAttributeMaxDynamicSharedMemorySize, SMEM_BYTES);
    cudaFuncSetAttribute(k_expand, cudaFuncAttributeMaxDynamicSharedMemorySize, SMEM_BYTES);
    cudaFuncSetAttribute(k_agg<true>, cudaFuncAttributeMaxDynamicSharedMemorySize, SMEM_BYTES);
    cudaFuncSetAttribute(k_agg<false>, cudaFuncAttributeMaxDynamicSharedMemorySize, SMEM_BYTES);

    // one-time weight rounding (tiny)
    k_round<<<(2048 * 512 / 4 + 255) / 256, 256>>>(Wemb, WembR, 2048 * 512 / 4);
    k_round<<<(6 * 262144 / 4 + 255) / 256, 256>>>(Wr0, WR0, 6 * 262144 / 4);
    k_round<<<(262144 / 4 + 255) / 256, 256>>>(Wl0, WR0 + 6u * 262144u, 262144 / 4);
    k_round<<<(6 * 262144 / 4 + 255) / 256, 256>>>(Wr1, WR1, 6 * 262144 / 4);
    k_round<<<(262144 / 4 + 255) / 256, 256>>>(Wl1, WR1 + 6u * 262144u, 262144 / 4);

    k_embed<<<dim3(4, 256), 256, SMEM_BYTES>>>(attn, WembR, bemb, X0);

    k_expand<<<dim3(28, 256), 256, SMEM_BYTES>>>(X0, WR0, Z);
    k_agg<true><<<dim3(4, 2, 128), 256, SMEM_BYTES>>>(E, Z, b0, X1);

    k_expand<<<dim3(28, 256), 256, SMEM_BYTES>>>(X1, WR1, Z);
    k_agg<false><<<dim3(4, 2, 128), 256, SMEM_BYTES>>>(E, Z, b1, out);
}

// round 5
// speedup vs baseline: 4.0528x; 1.0774x over previous
#include <cuda_runtime.h>
#include <cstdint>

// ---------------------------------------------------------------------------
// RGCNEncoder via mma.sync tf32 tensor cores.
// B=128, R=6, N=256, D_IN=2048, D_H=512
//
// CTA tile 128x128, K-chunk 32, 4 warps x (64x64) warp tiles, m16n8k8 tf32,
// 3-stage cp.async pipeline, fp32 accumulate. Internally-produced operands
// (X0, X1, Z, weights) stored pre-rounded to tf32 (no in-loop cvt); only
// external A operands (attn, rel_edges) are cvt.rna'd in-loop.
// ---------------------------------------------------------------------------

static __device__ float g_X0[32768u * 512u];
static __device__ float g_X1[32768u * 512u];
static __device__ float g_Z[128u * 7u * 256u * 512u];   // [b][r][n][d]
static __device__ float g_WembR[2048u * 512u];          // rounded W_embed
static __device__ float g_WR[2u][7u * 512u * 512u];     // rounded [r<6]=rel, [6]=loop

#define BM 128
#define BN 128
#define BK 32
#define ASTR 36     // BK + 4 pad   (4*gid+tig -> conflict-free frag loads)
#define BSTR 136    // BN + 8 pad   (8*tig+gid -> conflict-free frag loads)

static constexpr int AS_FLOATS = BM * ASTR;                    // 4608
static constexpr int BS_FLOATS = BK * BSTR;                    // 4352
static constexpr int STAGE_F   = AS_FLOATS + BS_FLOATS;        // 8960
static constexpr uint32_t AS_BYTES  = AS_FLOATS * 4;           // 18432
static constexpr uint32_t STAGE_B   = STAGE_F * 4;             // 35840
static constexpr int SMEM_BYTES = 3 * STAGE_B;                 // 107520

// ---- low-level helpers -----------------------------------------------------

__device__ __forceinline__ uint32_t smem_u32(const void* p) {
    uint32_t a;
    asm("{ .reg .u64 t; cvta.to.shared.u64 t, %1; cvt.u32.u64 %0, t; }"
        : "=r"(a) : "l"(p));
    return a;
}
__device__ __forceinline__ void cp_async16(uint32_t dst, const void* src) {
    asm volatile("cp.async.cg.shared.global [%0], [%1], 16;" ::"r"(dst), "l"(src));
}
__device__ __forceinline__ void cp_commit() {
    asm volatile("cp.async.commit_group;" ::: "memory");
}
template <int N>
__device__ __forceinline__ void cp_wait() {
    asm volatile("cp.async.wait_group %0;" ::"n"(N) : "memory");
}
__device__ __forceinline__ uint32_t f2tf(float x) {
    uint32_t r;
    asm("cvt.rna.tf32.f32 %0, %1;" : "=r"(r) : "f"(x));
    return r;
}
__device__ __forceinline__ float rnd(float x) {
    return __uint_as_float(f2tf(x));
}
__device__ __forceinline__ void mma8(float* c, const uint32_t* a, const uint32_t* b) {
    asm volatile(
        "mma.sync.aligned.m16n8k8.row.col.f32.tf32.tf32.f32 "
        "{%0,%1,%2,%3}, {%4,%5,%6,%7}, {%8,%9}, {%0,%1,%2,%3};"
        : "+f"(c[0]), "+f"(c[1]), "+f"(c[2]), "+f"(c[3])
        : "r"(a[0]), "r"(a[1]), "r"(a[2]), "r"(a[3]), "r"(b[0]), "r"(b[1]));
}

// 128x32 float tile (row-major, stride lda) -> padded smem, 128 threads
__device__ __forceinline__ void ld_tileA(uint32_t dst, const float* __restrict__ src,
                                         int lda, int tid) {
#pragma unroll
    for (int i = 0; i < 8; i++) {
        int idx = tid + i * 128;
        int row = idx >> 3, seg = idx & 7;
        cp_async16(dst + (uint32_t)(row * ASTR + seg * 4) * 4,
                   src + (size_t)row * lda + seg * 4);
    }
}
// 32x128 float tile (row-major, stride ldb) -> padded smem, 128 threads
__device__ __forceinline__ void ld_tileB(uint32_t dst, const float* __restrict__ src,
                                         int ldb, int tid) {
#pragma unroll
    for (int i = 0; i < 8; i++) {
        int idx = tid + i * 128;
        int row = idx >> 5, seg = idx & 31;
        cp_async16(dst + (uint32_t)(row * BSTR + seg * 4) * 4,
                   src + (size_t)row * ldb + seg * 4);
    }
}

// ---- shared mainloop -------------------------------------------------------
// 4 warps, each owns a 64x64 warp tile: wm = (wid>>1)*64, wn = (wid&1)*64.
// Per k=8 step: 16 A-LDS + 16 B-LDS feed 32 MMAs.

template <bool CVT_A, class F>
__device__ __forceinline__ void gemm_main(const F& f, int nc, float* sm,
                                          float acc[4][8][4]) {
    const int tid = threadIdx.x;
    const uint32_t sbase = smem_u32(sm);
    const int lane = tid & 31, wid = tid >> 5;
    const int gid = lane >> 2, tig = lane & 3;
    const int wm = (wid >> 1) * 64, wn = (wid & 1) * 64;
    const int athr = (wm + gid) * ASTR + tig;
    const int bthr = AS_FLOATS + tig * BSTR + wn + gid;

#pragma unroll
    for (int p = 0; p < 3; p++) {
        if (p < nc) {
            ld_tileA(sbase + p * STAGE_B, f.a(p), f.lda, tid);
            ld_tileB(sbase + p * STAGE_B + AS_BYTES, f.b(p), f.ldb, tid);
        }
        cp_commit();
    }

    int stage = 0;
    for (int c = 0; c < nc; c++) {
        cp_wait<2>();
        __syncthreads();
        const float* ap = sm + stage * STAGE_F + athr;
        const float* bp = sm + stage * STAGE_F + bthr;
#pragma unroll
        for (int kk = 0; kk < BK; kk += 8) {
            uint32_t a[4][4], b[8][2];
#pragma unroll
            for (int mt = 0; mt < 4; mt++) {
                const float* p0 = ap + mt * 16 * ASTR + kk;
                if (CVT_A) {
                    a[mt][0] = f2tf(p0[0]);
                    a[mt][1] = f2tf(p0[8 * ASTR]);
                    a[mt][2] = f2tf(p0[4]);
                    a[mt][3] = f2tf(p0[8 * ASTR + 4]);
                } else {
                    a[mt][0] = __float_as_uint(p0[0]);
                    a[mt][1] = __float_as_uint(p0[8 * ASTR]);
                    a[mt][2] = __float_as_uint(p0[4]);
                    a[mt][3] = __float_as_uint(p0[8 * ASTR + 4]);
                }
            }
#pragma unroll
            for (int nt = 0; nt < 8; nt++) {
                const float* q0 = bp + kk * BSTR + nt * 8;
                b[nt][0] = __float_as_uint(q0[0]);
                b[nt][1] = __float_as_uint(q0[4 * BSTR]);
            }
#pragma unroll
            for (int mt = 0; mt < 4; mt++)
#pragma unroll
                for (int nt = 0; nt < 8; nt++) mma8(acc[mt][nt], a[mt], b[nt]);
        }
        __syncthreads();
        if (c + 3 < nc) {
            ld_tileA(sbase + stage * STAGE_B, f.a(c + 3), f.lda, tid);
            ld_tileB(sbase + stage * STAGE_B + AS_BYTES, f.b(c + 3), f.ldb, tid);
        }
        cp_commit();
        stage = (stage == 2) ? 0 : stage + 1;
    }
}

__device__ __forceinline__ void zero_acc(float acc[4][8][4]) {
#pragma unroll
    for (int i = 0; i < 4; i++)
#pragma unroll
        for (int j = 0; j < 8; j++)
#pragma unroll
            for (int k = 0; k < 4; k++) acc[i][j][k] = 0.f;
}

// ---- address functors ------------------------------------------------------

struct LinAddr {
    const float *A, *B;
    int lda, ldb;
    __device__ const float* a(int c) const { return A + c * BK; }
    __device__ const float* b(int c) const { return B + (size_t)c * BK * ldb; }
};
struct AggAddr {
    const float *Eb, *Zb;
    int lda, ldb;
    __device__ const float* a(int c) const {
        return Eb + (size_t)(c >> 3) * 65536u + (c & 7) * BK;
    }
    __device__ const float* b(int c) const {
        return Zb + (size_t)(c >> 3) * 131072u + (size_t)(c & 7) * BK * 512;
    }
};

// ---- kernels ---------------------------------------------------------------

__global__ void __launch_bounds__(128, 2) k_embed(const float* __restrict__ attn,
                                                  const float* __restrict__ W,
                                                  const float* __restrict__ bias,
                                                  float* __restrict__ out) {
    extern __shared__ float sm[];
    const int bx = blockIdx.x, by = blockIdx.y;
    float acc[4][8][4];
    zero_acc(acc);

    LinAddr f{attn + (size_t)by * 128 * 2048, W + bx * 128, 2048, 512};
    gemm_main<true>(f, 64, sm, acc);

    const int tid = threadIdx.x, lane = tid & 31, wid = tid >> 5;
    const int gid = lane >> 2, tig = lane & 3;
    const int wm = (wid >> 1) * 64, wn = (wid & 1) * 64;
#pragma unroll
    for (int mt = 0; mt < 4; mt++) {
        int row = by * 128 + wm + mt * 16 + gid;
#pragma unroll
        for (int nt = 0; nt < 8; nt++) {
            int col = bx * 128 + wn + nt * 8 + tig * 2;
            float b0 = bias[col], b1 = bias[col + 1];
            float2 v0 = make_float2(rnd(fmaxf(acc[mt][nt][0] + b0, 0.f)),
                                    rnd(fmaxf(acc[mt][nt][1] + b1, 0.f)));
            float2 v1 = make_float2(rnd(fmaxf(acc[mt][nt][2] + b0, 0.f)),
                                    rnd(fmaxf(acc[mt][nt][3] + b1, 0.f)));
            *(float2*)&out[(size_t)row * 512 + col] = v0;
            *(float2*)&out[(size_t)(row + 8) * 512 + col] = v1;
        }
    }
}

__global__ void __launch_bounds__(128, 2) k_expand(const float* __restrict__ X,
                                                   const float* __restrict__ WR,
                                                   float* __restrict__ Z) {
    extern __shared__ float sm[];
    const int bx = blockIdx.x, by = blockIdx.y;
    const int r = bx >> 2, d0 = (bx & 3) * 128;
    float acc[4][8][4];
    zero_acc(acc);

    LinAddr f{X + (size_t)by * 128 * 512, WR + (size_t)r * 262144u + d0, 512, 512};
    gemm_main<false>(f, 16, sm, acc);

    const int tid = threadIdx.x, lane = tid & 31, wid = tid >> 5;
    const int gid = lane >> 2, tig = lane & 3;
    const int wm = (wid >> 1) * 64, wn = (wid & 1) * 64;
#pragma unroll
    for (int mt = 0; mt < 4; mt++) {
        int m = by * 128 + wm + mt * 16 + gid;
        int b = m >> 8, n = m & 255;
        size_t zb = ((size_t)b * 7 + r) * 256u;
#pragma unroll
        for (int nt = 0; nt < 8; nt++) {
            int d = d0 + wn + nt * 8 + tig * 2;
            *(float2*)&Z[(zb + n) * 512u + d] =
                make_float2(rnd(acc[mt][nt][0]), rnd(acc[mt][nt][1]));
            *(float2*)&Z[(zb + n + 8) * 512u + d] =
                make_float2(rnd(acc[mt][nt][2]), rnd(acc[mt][nt][3]));
        }
    }
}

template <bool ROUND>
__global__ void __launch_bounds__(128, 2) k_agg(const float* __restrict__ E,
                                                const float* __restrict__ Z,
                                                const float* __restrict__ bias,
                                                float* __restrict__ out) {
    extern __shared__ float sm[];
    const int bx = blockIdx.x, by = blockIdx.y, b = blockIdx.z;
    float acc[4][8][4];
    zero_acc(acc);

    AggAddr f{E + (size_t)b * 393216u + (size_t)(by * 128) * 256u,
              Z + (size_t)b * 917504u + bx * 128, 256, 512};
    gemm_main<true>(f, 48, sm, acc);

    const float* Zl = Z + (size_t)b * 917504u + 6u * 131072u;
    const int tid = threadIdx.x, lane = tid & 31, wid = tid >> 5;
    const int gid = lane >> 2, tig = lane & 3;
    const int wm = (wid >> 1) * 64, wn = (wid & 1) * 64;
#pragma unroll
    for (int mt = 0; mt < 4; mt++) {
        int i = by * 128 + wm + mt * 16 + gid;
#pragma unroll
        for (int nt = 0; nt < 8; nt++) {
            int d = bx * 128 + wn + nt * 8 + tig * 2;
            float b0 = bias[d], b1 = bias[d + 1];
            float2 l0 = *(const float2*)&Zl[(size_t)i * 512 + d];
            float2 l1 = *(const float2*)&Zl[(size_t)(i + 8) * 512 + d];
            float r0 = fmaxf(acc[mt][nt][0] + l0.x + b0, 0.f);
            float r1 = fmaxf(acc[mt][nt][1] + l0.y + b1, 0.f);
            float r2 = fmaxf(acc[mt][nt][2] + l1.x + b0, 0.f);
            float r3 = fmaxf(acc[mt][nt][3] + l1.y + b1, 0.f);
            float2 v0, v1;
            if (ROUND) {
                v0 = make_float2(rnd(r0), rnd(r1));
                v1 = make_float2(rnd(r2), rnd(r3));
            } else {
                v0 = make_float2(r0, r1);
                v1 = make_float2(r2, r3);
            }
            *(float2*)&out[((size_t)b * 256 + i) * 512 + d] = v0;
            *(float2*)&out[((size_t)b * 256 + i + 8) * 512 + d] = v1;
        }
    }
}

// elementwise tf32 rounding pass (for weights)
__global__ void k_round(const float* __restrict__ src, float* __restrict__ dst,
                        int n4) {
    int i = blockIdx.x * blockDim.x + threadIdx.x;
    if (i < n4) {
        float4 v = ((const float4*)src)[i];
        v.x = rnd(v.x); v.y = rnd(v.y); v.z = rnd(v.z); v.w = rnd(v.w);
        ((float4*)dst)[i] = v;
    }
}

// ---------------------------------------------------------------------------

extern "C" void kernel_launch(void* const* d_in, const int* in_sizes, int n_in,
                              void* d_out, int out_size) {
    const float* attn = (const float*)d_in[0];
    const float* E    = (const float*)d_in[1];
    const float* Wemb = (const float*)d_in[2];
    const float* bemb = (const float*)d_in[3];
    const float* Wr0  = (const float*)d_in[4];
    const float* Wl0  = (const float*)d_in[5];
    const float* b0   = (const float*)d_in[6];
    const float* Wr1  = (const float*)d_in[7];
    const float* Wl1  = (const float*)d_in[8];
    const float* b1   = (const float*)d_in[9];
    float* out = (float*)d_out;

    float *X0, *X1, *Z, *WembR, *WR;
    cudaGetSymbolAddress((void**)&X0, g_X0);
    cudaGetSymbolAddress((void**)&X1, g_X1);
    cudaGetSymbolAddress((void**)&Z, g_Z);
    cudaGetSymbolAddress((void**)&WembR, g_WembR);
    cudaGetSymbolAddress((void**)&WR, g_WR);
    float* WR0 = WR;
    float* WR1 = WR + 7u * 262144u;

    cudaFuncSetAttribute(k_embed, cudaFuncAttributeMaxDynamicSharedMemorySize, SMEM_BYTES);
    cudaFuncSetAttribute(k_expand, cudaFuncAttributeMaxDynamicSharedMemorySize, SMEM_BYTES);
    cudaFuncSetAttribute(k_agg<true>, cudaFuncAttributeMaxDynamicSharedMemorySize, SMEM_BYTES);
    cudaFuncSetAttribute(k_agg<false>, cudaFuncAttributeMaxDynamicSharedMemorySize, SMEM_BYTES);

    // one-time weight rounding (tiny)
    k_round<<<(2048 * 512 / 4 + 255) / 256, 256>>>(Wemb, WembR, 2048 * 512 / 4);
    k_round<<<(6 * 262144 / 4 + 255) / 256, 256>>>(Wr0, WR0, 6 * 262144 / 4);
    k_round<<<(262144 / 4 + 255) / 256, 256>>>(Wl0, WR0 + 6u * 262144u, 262144 / 4);
    k_round<<<(6 * 262144 / 4 + 255) / 256, 256>>>(Wr1, WR1, 6 * 262144 / 4);
    k_round<<<(262144 / 4 + 255) / 256, 256>>>(Wl1, WR1 + 6u * 262144u, 262144 / 4);

    k_embed<<<dim3(4, 256), 128, SMEM_BYTES>>>(attn, WembR, bemb, X0);

    k_expand<<<dim3(28, 256), 128, SMEM_BYTES>>>(X0, WR0, Z);
    k_agg<true><<<dim3(4, 2, 128), 128, SMEM_BYTES>>>(E, Z, b0, X1);

    k_expand<<<dim3(28, 256), 128, SMEM_BYTES>>>(X1, WR1, Z);
    k_agg<false><<<dim3(4, 2, 128), 128, SMEM_BYTES>>>(E, Z, b1, out);
}

// round 6
// speedup vs baseline: 5.7064x; 1.4080x over previous
#include <cuda_runtime.h>
#include <cuda_fp16.h>
#include <cstdint>

// ---------------------------------------------------------------------------
// RGCNEncoder via mma.sync fp16 tensor cores (m16n8k16, fp32 accumulate).
// B=128, R=6, N=256, D_IN=2048, D_H=512
//
//   x0 = relu(attn @ W_embed + b_embed)
//   layer l: Z[b,r] = x[b] @ W_rel_l[r] (r<6), Z[b,6] = x[b] @ W_loop_l
//            out[b] = relu(sum_{r=0..6} E_ext[b,r] @ Z[b,r] + bias)
//            with E_ext[b,6] = Identity (self-loop folded into the GEMM).
//
// CTA tile 128x128, K-chunk 32, 4 warps x (64x64), 3-stage cp.async pipeline.
// Both operands stored K-contiguous ([m][k] / [n][k]) in fp16:
//   - weights pre-transposed+converted
//   - expand computes the transposed GEMM (M=d, N=node) so Z is written
//     directly as [b][r][d][j], which is agg's B layout.
// ---------------------------------------------------------------------------

static __device__ __half g_attnH[32768u * 2048u];
static __device__ __half g_EH[128u * 7u * 256u * 256u];   // slot 6 = identity
static __device__ __half g_WembT[512u * 2048u];           // [h][din]
static __device__ __half g_WT[2][7u * 512u * 512u];       // [r][dout][din]
static __device__ __half g_X0[32768u * 512u];
static __device__ __half g_X1[32768u * 512u];
static __device__ __half g_Z[128u * 7u * 512u * 256u];    // [b][r][d][j]

#define BK 32
#define RSTR 40   // padded row stride in halves (conflict-free frag loads)

static constexpr int AS_H = 128 * RSTR;               // 5120 halves / operand
static constexpr int STAGE_H = 2 * AS_H;              // 10240
static constexpr uint32_t AS_BYTES = AS_H * 2;        // 10240
static constexpr uint32_t STAGE_BYTES = STAGE_H * 2;  // 20480
static constexpr int SMEM_BYTES = 3 * STAGE_BYTES;    // 61440

// ---- low-level helpers -----------------------------------------------------

__device__ __forceinline__ uint32_t smem_u32(const void* p) {
    uint32_t a;
    asm("{ .reg .u64 t; cvta.to.shared.u64 t, %1; cvt.u32.u64 %0, t; }"
        : "=r"(a) : "l"(p));
    return a;
}
__device__ __forceinline__ void cp_async16(uint32_t dst, const void* src) {
    asm volatile("cp.async.cg.shared.global [%0], [%1], 16;" ::"r"(dst), "l"(src));
}
__device__ __forceinline__ void cp_commit() {
    asm volatile("cp.async.commit_group;" ::: "memory");
}
template <int N>
__device__ __forceinline__ void cp_wait() {
    asm volatile("cp.async.wait_group %0;" ::"n"(N) : "memory");
}
__device__ __forceinline__ uint32_t h2u(__half2 h) {
    return *reinterpret_cast<uint32_t*>(&h);
}
__device__ __forceinline__ void mma16(float* c, const uint32_t* a, const uint32_t* b) {
    asm volatile(
        "mma.sync.aligned.m16n8k16.row.col.f32.f16.f16.f32 "
        "{%0,%1,%2,%3}, {%4,%5,%6,%7}, {%8,%9}, {%0,%1,%2,%3};"
        : "+f"(c[0]), "+f"(c[1]), "+f"(c[2]), "+f"(c[3])
        : "r"(a[0]), "r"(a[1]), "r"(a[2]), "r"(a[3]), "r"(b[0]), "r"(b[1]));
}

// 128 rows x 32 halves (64B/row) tile -> padded smem, 128 threads
__device__ __forceinline__ void ld_tile(uint32_t dst, const __half* __restrict__ src,
                                        int ldk, int tid) {
#pragma unroll
    for (int i = 0; i < 4; i++) {
        int idx = tid + i * 128;
        int row = idx >> 2, seg = idx & 3;
        cp_async16(dst + (uint32_t)(row * (RSTR * 2) + seg * 16),
                   src + (size_t)row * ldk + seg * 8);
    }
}

// ---- shared mainloop -------------------------------------------------------
// 4 warps, each a 64x64 warp tile. Per k16 step: 16 A-LDS.32 + 16 B-LDS.32
// feed 32 m16n8k16 MMAs.

template <class F>
__device__ __forceinline__ void gemm_main(const F& f, int nc, __half* sm,
                                          float acc[4][8][4]) {
    const int tid = threadIdx.x;
    const uint32_t sbase = smem_u32(sm);
    const int lane = tid & 31, wid = tid >> 5;
    const int gid = lane >> 2, tig = lane & 3;
    const int wm = (wid >> 1) * 64, wn = (wid & 1) * 64;
    const int athr = (wm + gid) * RSTR + 2 * tig;
    const int bthr = AS_H + (wn + gid) * RSTR + 2 * tig;

#pragma unroll
    for (int p = 0; p < 3; p++) {
        if (p < nc) {
            ld_tile(sbase + p * STAGE_BYTES, f.a(p), f.lda, tid);
            ld_tile(sbase + p * STAGE_BYTES + AS_BYTES, f.b(p), f.ldb, tid);
        }
        cp_commit();
    }

    int stage = 0;
    for (int c = 0; c < nc; c++) {
        cp_wait<2>();
        __syncthreads();
        const __half* ap = sm + stage * STAGE_H + athr;
        const __half* bp = sm + stage * STAGE_H + bthr;
#pragma unroll
        for (int kk = 0; kk < BK; kk += 16) {
            uint32_t a[4][4], b[8][2];
#pragma unroll
            for (int mt = 0; mt < 4; mt++) {
                const __half* p0 = ap + mt * 16 * RSTR + kk;
                a[mt][0] = *(const uint32_t*)(p0);
                a[mt][1] = *(const uint32_t*)(p0 + 8 * RSTR);
                a[mt][2] = *(const uint32_t*)(p0 + 8);
                a[mt][3] = *(const uint32_t*)(p0 + 8 * RSTR + 8);
            }
#pragma unroll
            for (int nt = 0; nt < 8; nt++) {
                const __half* q0 = bp + nt * 8 * RSTR + kk;
                b[nt][0] = *(const uint32_t*)(q0);
                b[nt][1] = *(const uint32_t*)(q0 + 8);
            }
#pragma unroll
            for (int mt = 0; mt < 4; mt++)
#pragma unroll
                for (int nt = 0; nt < 8; nt++) mma16(acc[mt][nt], a[mt], b[nt]);
        }
        __syncthreads();
        if (c + 3 < nc) {
            ld_tile(sbase + stage * STAGE_BYTES, f.a(c + 3), f.lda, tid);
            ld_tile(sbase + stage * STAGE_BYTES + AS_BYTES, f.b(c + 3), f.ldb, tid);
        }
        cp_commit();
        stage = (stage == 2) ? 0 : stage + 1;
    }
}

__device__ __forceinline__ void zero_acc(float acc[4][8][4]) {
#pragma unroll
    for (int i = 0; i < 4; i++)
#pragma unroll
        for (int j = 0; j < 8; j++)
#pragma unroll
            for (int k = 0; k < 4; k++) acc[i][j][k] = 0.f;
}

// ---- address functors ------------------------------------------------------

struct LinAddr {
    const __half *A, *B;
    int lda, ldb;
    __device__ const __half* a(int c) const { return A + c * BK; }
    __device__ const __half* b(int c) const { return B + c * BK; }
};
struct AggAddr {
    const __half *Eb, *Zb;
    int lda, ldb;
    __device__ const __half* a(int c) const {
        return Eb + (size_t)(c >> 3) * 65536u + (c & 7) * BK;
    }
    __device__ const __half* b(int c) const {
        return Zb + (size_t)(c >> 3) * 131072u + (c & 7) * BK;
    }
};

// ---- kernels ---------------------------------------------------------------

// embed: X0[node][h] = relu(attnH @ WembT^T + bias), fp16 out
__global__ void __launch_bounds__(128, 2) k_embed(const __half* __restrict__ attn,
                                                  const __half* __restrict__ WT,
                                                  const float* __restrict__ bias,
                                                  __half* __restrict__ out) {
    extern __shared__ char smraw[];
    __half* sm = (__half*)smraw;
    const int bx = blockIdx.x, by = blockIdx.y;
    float acc[4][8][4];
    zero_acc(acc);

    LinAddr f{attn + (size_t)by * 128 * 2048, WT + (size_t)bx * 128 * 2048,
              2048, 2048};
    gemm_main(f, 64, sm, acc);

    const int tid = threadIdx.x, lane = tid & 31, wid = tid >> 5;
    const int gid = lane >> 2, tig = lane & 3;
    const int wm = (wid >> 1) * 64, wn = (wid & 1) * 64;
#pragma unroll
    for (int mt = 0; mt < 4; mt++) {
        int row = by * 128 + wm + mt * 16 + gid;
#pragma unroll
        for (int nt = 0; nt < 8; nt++) {
            int col = bx * 128 + wn + nt * 8 + 2 * tig;
            float b0 = bias[col], b1 = bias[col + 1];
            __half2 h0 = __floats2half2_rn(fmaxf(acc[mt][nt][0] + b0, 0.f),
                                           fmaxf(acc[mt][nt][1] + b1, 0.f));
            __half2 h1 = __floats2half2_rn(fmaxf(acc[mt][nt][2] + b0, 0.f),
                                           fmaxf(acc[mt][nt][3] + b1, 0.f));
            *(uint32_t*)&out[(size_t)row * 512 + col] = h2u(h0);
            *(uint32_t*)&out[(size_t)(row + 8) * 512 + col] = h2u(h1);
        }
    }
}

// expand (transposed GEMM): Z[b][r][d][j] = (WT[r] @ X^T)[d][node]
__global__ void __launch_bounds__(128, 2) k_expand(const __half* __restrict__ X,
                                                   const __half* __restrict__ WT,
                                                   __half* __restrict__ Z) {
    extern __shared__ char smraw[];
    __half* sm = (__half*)smraw;
    const int bx = blockIdx.x, by = blockIdx.y;
    const int r = bx >> 2, d0 = (bx & 3) * 128;
    float acc[4][8][4];
    zero_acc(acc);

    LinAddr f{WT + (size_t)r * 262144u + (size_t)d0 * 512,
              X + (size_t)by * 128 * 512, 512, 512};
    gemm_main(f, 16, sm, acc);

    const int tid = threadIdx.x, lane = tid & 31, wid = tid >> 5;
    const int gid = lane >> 2, tig = lane & 3;
    const int wm = (wid >> 1) * 64, wn = (wid & 1) * 64;
#pragma unroll
    for (int mt = 0; mt < 4; mt++) {
        int d = d0 + wm + mt * 16 + gid;
#pragma unroll
        for (int nt = 0; nt < 8; nt++) {
            int m = by * 128 + wn + nt * 8 + 2 * tig;   // global node
            int b = m >> 8, j = m & 255;
            size_t zb = ((size_t)b * 7 + r) * 512u;
            __half2 h0 = __floats2half2_rn(acc[mt][nt][0], acc[mt][nt][1]);
            __half2 h1 = __floats2half2_rn(acc[mt][nt][2], acc[mt][nt][3]);
            *(uint32_t*)&Z[(zb + d) * 256u + j] = h2u(h0);
            *(uint32_t*)&Z[(zb + d + 8) * 256u + j] = h2u(h1);
        }
    }
}

// agg: out[b,i,d] = relu(sum_{r=0..6,j} EH[b,r,i,j] * Z[b,r,d,j] + bias[d])
template <bool HALF_OUT>
__global__ void __launch_bounds__(128, 2) k_agg(const __half* __restrict__ EH,
                                                const __half* __restrict__ Z,
                                                const float* __restrict__ bias,
                                                void* __restrict__ outv) {
    extern __shared__ char smraw[];
    __half* sm = (__half*)smraw;
    const int bx = blockIdx.x, by = blockIdx.y, b = blockIdx.z;
    float acc[4][8][4];
    zero_acc(acc);

    AggAddr f{EH + (size_t)b * 458752u + (size_t)(by * 128) * 256u,
              Z + (size_t)b * 917504u + (size_t)(bx * 128) * 256u, 256, 256};
    gemm_main(f, 56, sm, acc);

    const int tid = threadIdx.x, lane = tid & 31, wid = tid >> 5;
    const int gid = lane >> 2, tig = lane & 3;
    const int wm = (wid >> 1) * 64, wn = (wid & 1) * 64;
#pragma unroll
    for (int mt = 0; mt < 4; mt++) {
        int i = by * 128 + wm + mt * 16 + gid;
#pragma unroll
        for (int nt = 0; nt < 8; nt++) {
            int d = bx * 128 + wn + nt * 8 + 2 * tig;
            float b0 = bias[d], b1 = bias[d + 1];
            float r0 = fmaxf(acc[mt][nt][0] + b0, 0.f);
            float r1 = fmaxf(acc[mt][nt][1] + b1, 0.f);
            float r2 = fmaxf(acc[mt][nt][2] + b0, 0.f);
            float r3 = fmaxf(acc[mt][nt][3] + b1, 0.f);
            size_t o0 = ((size_t)b * 256 + i) * 512 + d;
            size_t o1 = ((size_t)b * 256 + i + 8) * 512 + d;
            if (HALF_OUT) {
                __half* out = (__half*)outv;
                *(uint32_t*)&out[o0] = h2u(__floats2half2_rn(r0, r1));
                *(uint32_t*)&out[o1] = h2u(__floats2half2_rn(r2, r3));
            } else {
                float* out = (float*)outv;
                *(float2*)&out[o0] = make_float2(r0, r1);
                *(float2*)&out[o1] = make_float2(r2, r3);
            }
        }
    }
}

// ---- conversion / transpose pre-kernels ------------------------------------

__global__ void k_cvt8(const float* __restrict__ src, __half* __restrict__ dst,
                       int n8) {
    int i = blockIdx.x * blockDim.x + threadIdx.x;
    if (i < n8) {
        const float4* s4 = (const float4*)src;
        float4 v0 = s4[2 * i], v1 = s4[2 * i + 1];
        uint4 o;
        o.x = h2u(__floats2half2_rn(v0.x, v0.y));
        o.y = h2u(__floats2half2_rn(v0.z, v0.w));
        o.z = h2u(__floats2half2_rn(v1.x, v1.y));
        o.w = h2u(__floats2half2_rn(v1.z, v1.w));
        ((uint4*)dst)[i] = o;
    }
}

// E fp32 [b][6][i][j] -> fp16 [b][7][i][j], slot 6 = identity
__global__ void k_cvtE(const float* __restrict__ E, __half* __restrict__ EH) {
    int b = blockIdx.z, r = blockIdx.y;
    int g = blockIdx.x * blockDim.x + threadIdx.x;   // 0..16383
    int i = g >> 6, j0 = (g & 63) * 4;
    uint2 o;
    if (r < 6) {
        float4 v = *(const float4*)&E[(((size_t)b * 6 + r) * 256 + i) * 256 + j0];
        o.x = h2u(__floats2half2_rn(v.x, v.y));
        o.y = h2u(__floats2half2_rn(v.z, v.w));
    } else {
        o.x = h2u(__floats2half2_rn(j0 == i ? 1.f : 0.f, j0 + 1 == i ? 1.f : 0.f));
        o.y = h2u(__floats2half2_rn(j0 + 2 == i ? 1.f : 0.f, j0 + 3 == i ? 1.f : 0.f));
    }
    *(uint2*)&EH[(((size_t)b * 7 + r) * 256 + i) * 256 + j0] = o;
}

// transpose + convert: src fp32 [R][C] -> dst fp16 [C][R]
__global__ void k_tcvt(const float* __restrict__ src, __half* __restrict__ dst,
                       int R, int C) {
    __shared__ float t[32][33];
    int bx = blockIdx.x * 32, by = blockIdx.y * 32;
    int x = threadIdx.x, y = threadIdx.y;
#pragma unroll
    for (int j = 0; j < 32; j += 8)
        t[y + j][x] = src[(size_t)(by + y + j) * C + bx + x];
    __syncthreads();
#pragma unroll
    for (int j = 0; j < 32; j += 8)
        dst[(size_t)(bx + y + j) * R + by + x] = __float2half_rn(t[x][y + j]);
}

// ---------------------------------------------------------------------------

extern "C" void kernel_launch(void* const* d_in, const int* in_sizes, int n_in,
                              void* d_out, int out_size) {
    const float* attn = (const float*)d_in[0];
    const float* E    = (const float*)d_in[1];
    const float* Wemb = (const float*)d_in[2];
    const float* bemb = (const float*)d_in[3];
    const float* Wr0  = (const float*)d_in[4];
    const float* Wl0  = (const float*)d_in[5];
    const float* b0   = (const float*)d_in[6];
    const float* Wr1  = (const float*)d_in[7];
    const float* Wl1  = (const float*)d_in[8];
    const float* b1   = (const float*)d_in[9];
    float* out = (float*)d_out;

    __half *attnH, *EH, *WembT, *WT, *X0, *X1, *Z;
    cudaGetSymbolAddress((void**)&attnH, g_attnH);
    cudaGetSymbolAddress((void**)&EH, g_EH);
    cudaGetSymbolAddress((void**)&WembT, g_WembT);
    cudaGetSymbolAddress((void**)&WT, g_WT);
    cudaGetSymbolAddress((void**)&X0, g_X0);
    cudaGetSymbolAddress((void**)&X1, g_X1);
    cudaGetSymbolAddress((void**)&Z, g_Z);
    __half* WT0 = WT;
    __half* WT1 = WT + 7u * 262144u;

    cudaFuncSetAttribute(k_embed, cudaFuncAttributeMaxDynamicSharedMemorySize, SMEM_BYTES);
    cudaFuncSetAttribute(k_expand, cudaFuncAttributeMaxDynamicSharedMemorySize, SMEM_BYTES);
    cudaFuncSetAttribute(k_agg<true>, cudaFuncAttributeMaxDynamicSharedMemorySize, SMEM_BYTES);
    cudaFuncSetAttribute(k_agg<false>, cudaFuncAttributeMaxDynamicSharedMemorySize, SMEM_BYTES);

    // conversions
    k_cvt8<<<32768, 256>>>(attn, attnH, 32768 * 2048 / 8);
    k_cvtE<<<dim3(64, 7, 128), 256>>>(E, EH);
    dim3 tt(32, 8);
    k_tcvt<<<dim3(16, 64), tt>>>(Wemb, WembT, 2048, 512);
    for (int r = 0; r < 7; r++) {
        k_tcvt<<<dim3(16, 16), tt>>>(r < 6 ? Wr0 + (size_t)r * 262144 : Wl0,
                                     WT0 + (size_t)r * 262144, 512, 512);
        k_tcvt<<<dim3(16, 16), tt>>>(r < 6 ? Wr1 + (size_t)r * 262144 : Wl1,
                                     WT1 + (size_t)r * 262144, 512, 512);
    }

    k_embed<<<dim3(4, 256), 128, SMEM_BYTES>>>(attnH, WembT, bemb, X0);

    k_expand<<<dim3(28, 256), 128, SMEM_BYTES>>>(X0, WT0, Z);
    k_agg<true><<<dim3(4, 2, 128), 128, SMEM_BYTES>>>(EH, Z, b0, X1);

    k_expand<<<dim3(28, 256), 128, SMEM_BYTES>>>(X1, WT1, Z);
    k_agg<false><<<dim3(4, 2, 128), 128, SMEM_BYTES>>>(EH, Z, b1, out);
}

// round 7
// speedup vs baseline: 6.4278x; 1.1264x over previous
#include <cuda_runtime.h>
#include <cuda_fp16.h>
#include <cstdint>

// ---------------------------------------------------------------------------
// RGCNEncoder via mma.sync fp16 tensor cores (m16n8k16, fp32 accumulate),
// ldmatrix fragment loads, BK=64 K-chunks, 3-stage cp.async pipeline.
// B=128, R=6, N=256, D_IN=2048, D_H=512
//
//   x0 = relu(attn @ W_embed + b_embed)
//   layer l: Z[b,r] = x[b] @ W_rel_l[r] (r<6), Z[b,6] = x[b] @ W_loop_l
//            out[b] = relu(sum_{r=0..6} E_ext[b,r] @ Z[b,r] + bias),
//            E_ext[b,6] = Identity (self-loop folded into the GEMM).
//
// CTA tile 128x128, 4 warps x (64x64). Both operands K-contiguous fp16:
// weights pre-transposed+converted; expand computes the transposed GEMM so
// Z lands as [b][r][d][j] = agg's B layout.
// ---------------------------------------------------------------------------

static __device__ __half g_attnH[32768u * 2048u];
static __device__ __half g_EH[128u * 7u * 256u * 256u];   // slot 6 = identity
static __device__ __half g_WembT[512u * 2048u];           // [h][din]
static __device__ __half g_WT[2][7u * 512u * 512u];       // [r][dout][din]
static __device__ __half g_X0[32768u * 512u];
static __device__ __half g_X1[32768u * 512u];
static __device__ __half g_Z[128u * 7u * 512u * 256u];    // [b][r][d][j]

#define BK 64
#define RSTR 72   // BK + 8 pad (halves): 144B row stride, conflict-free ldmatrix

static constexpr int AS_H = 128 * RSTR;                 // 9216 halves / operand
static constexpr int STAGE_H = 2 * AS_H;                // 18432
static constexpr uint32_t AS_BYTES = AS_H * 2;          // 18432
static constexpr uint32_t STAGE_BYTES = STAGE_H * 2;    // 36864
static constexpr int SMEM_BYTES = 3 * STAGE_BYTES;      // 110592

// ---- low-level helpers -----------------------------------------------------

__device__ __forceinline__ uint32_t smem_u32(const void* p) {
    uint32_t a;
    asm("{ .reg .u64 t; cvta.to.shared.u64 t, %1; cvt.u32.u64 %0, t; }"
        : "=r"(a) : "l"(p));
    return a;
}
__device__ __forceinline__ void cp_async16(uint32_t dst, const void* src) {
    asm volatile("cp.async.cg.shared.global [%0], [%1], 16;" ::"r"(dst), "l"(src));
}
__device__ __forceinline__ void cp_commit() {
    asm volatile("cp.async.commit_group;" ::: "memory");
}
template <int N>
__device__ __forceinline__ void cp_wait() {
    asm volatile("cp.async.wait_group %0;" ::"n"(N) : "memory");
}
__device__ __forceinline__ uint32_t h2u(__half2 h) {
    return *reinterpret_cast<uint32_t*>(&h);
}
__device__ __forceinline__ void ldm_x4(uint32_t& r0, uint32_t& r1, uint32_t& r2,
                                       uint32_t& r3, uint32_t addr) {
    asm volatile("ldmatrix.sync.aligned.m8n8.x4.shared.b16 {%0,%1,%2,%3}, [%4];"
                 : "=r"(r0), "=r"(r1), "=r"(r2), "=r"(r3) : "r"(addr));
}
__device__ __forceinline__ void mma16(float* c, const uint32_t* a, const uint32_t* b) {
    asm volatile(
        "mma.sync.aligned.m16n8k16.row.col.f32.f16.f16.f32 "
        "{%0,%1,%2,%3}, {%4,%5,%6,%7}, {%8,%9}, {%0,%1,%2,%3};"
        : "+f"(c[0]), "+f"(c[1]), "+f"(c[2]), "+f"(c[3])
        : "r"(a[0]), "r"(a[1]), "r"(a[2]), "r"(a[3]), "r"(b[0]), "r"(b[1]));
}

// 128 rows x 64 halves (128B/row) tile -> padded smem, 128 threads
__device__ __forceinline__ void ld_tile(uint32_t dst, const __half* __restrict__ src,
                                        int ldk, int tid) {
#pragma unroll
    for (int i = 0; i < 8; i++) {
        int idx = tid + i * 128;
        int row = idx >> 3, seg = idx & 7;
        cp_async16(dst + (uint32_t)(row * (RSTR * 2) + seg * 16),
                   src + (size_t)row * ldk + seg * 8);
    }
}

// ---- shared mainloop -------------------------------------------------------
// 4 warps, each a 64x64 warp tile. Per k16 step: 4 A-ldmatrix.x4 +
// 4 B-ldmatrix.x4 feed 32 m16n8k16 MMAs.

template <class F>
__device__ __forceinline__ void gemm_main(const F& f, int nc, __half* sm,
                                          float acc[4][8][4]) {
    const int tid = threadIdx.x;
    const uint32_t sbase = smem_u32(sm);
    const int lane = tid & 31, wid = tid >> 5;
    const int wm = (wid >> 1) * 64, wn = (wid & 1) * 64;

    // ldmatrix per-lane byte offsets within the tile
    const int l7 = lane & 7, lb3 = (lane >> 3) & 1, lb4 = lane >> 4;
    const uint32_t aOff = (uint32_t)((wm + l7 + lb3 * 8) * RSTR + lb4 * 8) * 2;
    const uint32_t bOff = AS_BYTES +
        (uint32_t)((wn + l7 + lb4 * 8) * RSTR + lb3 * 8) * 2;

#pragma unroll
    for (int p = 0; p < 3; p++) {
        if (p < nc) {
            ld_tile(sbase + p * STAGE_BYTES, f.a(p), f.lda, tid);
            ld_tile(sbase + p * STAGE_BYTES + AS_BYTES, f.b(p), f.ldb, tid);
        }
        cp_commit();
    }

    int stage = 0;
    for (int c = 0; c < nc; c++) {
        cp_wait<2>();
        __syncthreads();
        const uint32_t abase = sbase + stage * STAGE_BYTES + aOff;
        const uint32_t bbase = sbase + stage * STAGE_BYTES + bOff;
#pragma unroll
        for (int kk = 0; kk < BK; kk += 16) {
            uint32_t a[4][4], b[8][2];
#pragma unroll
            for (int mt = 0; mt < 4; mt++)
                ldm_x4(a[mt][0], a[mt][1], a[mt][2], a[mt][3],
                       abase + (uint32_t)(mt * 16 * RSTR + kk) * 2);
#pragma unroll
            for (int p = 0; p < 4; p++)
                ldm_x4(b[2 * p][0], b[2 * p][1], b[2 * p + 1][0], b[2 * p + 1][1],
                       bbase + (uint32_t)(p * 16 * RSTR + kk) * 2);
#pragma unroll
            for (int mt = 0; mt < 4; mt++)
#pragma unroll
                for (int nt = 0; nt < 8; nt++) mma16(acc[mt][nt], a[mt], b[nt]);
        }
        __syncthreads();
        if (c + 3 < nc) {
            ld_tile(sbase + stage * STAGE_BYTES, f.a(c + 3), f.lda, tid);
            ld_tile(sbase + stage * STAGE_BYTES + AS_BYTES, f.b(c + 3), f.ldb, tid);
        }
        cp_commit();
        stage = (stage == 2) ? 0 : stage + 1;
    }
}

__device__ __forceinline__ void zero_acc(float acc[4][8][4]) {
#pragma unroll
    for (int i = 0; i < 4; i++)
#pragma unroll
        for (int j = 0; j < 8; j++)
#pragma unroll
            for (int k = 0; k < 4; k++) acc[i][j][k] = 0.f;
}

// ---- address functors ------------------------------------------------------

struct LinAddr {
    const __half *A, *B;
    int lda, ldb;
    __device__ const __half* a(int c) const { return A + c * BK; }
    __device__ const __half* b(int c) const { return B + c * BK; }
};
struct AggAddr {
    const __half *Eb, *Zb;
    int lda, ldb;
    __device__ const __half* a(int c) const {
        return Eb + (size_t)(c >> 2) * 65536u + (c & 3) * BK;
    }
    __device__ const __half* b(int c) const {
        return Zb + (size_t)(c >> 2) * 131072u + (c & 3) * BK;
    }
};

// ---- kernels ---------------------------------------------------------------

// embed: X0[node][h] = relu(attnH @ WembT^T + bias), fp16 out
__global__ void __launch_bounds__(128, 2) k_embed(const __half* __restrict__ attn,
                                                  const __half* __restrict__ WT,
                                                  const float* __restrict__ bias,
                                                  __half* __restrict__ out) {
    extern __shared__ char smraw[];
    __half* sm = (__half*)smraw;
    const int bx = blockIdx.x, by = blockIdx.y;
    float acc[4][8][4];
    zero_acc(acc);

    LinAddr f{attn + (size_t)by * 128 * 2048, WT + (size_t)bx * 128 * 2048,
              2048, 2048};
    gemm_main(f, 32, sm, acc);

    const int tid = threadIdx.x, lane = tid & 31, wid = tid >> 5;
    const int gid = lane >> 2, tig = lane & 3;
    const int wm = (wid >> 1) * 64, wn = (wid & 1) * 64;
#pragma unroll
    for (int mt = 0; mt < 4; mt++) {
        int row = by * 128 + wm + mt * 16 + gid;
#pragma unroll
        for (int nt = 0; nt < 8; nt++) {
            int col = bx * 128 + wn + nt * 8 + 2 * tig;
            float b0 = bias[col], b1 = bias[col + 1];
            __half2 h0 = __floats2half2_rn(fmaxf(acc[mt][nt][0] + b0, 0.f),
                                           fmaxf(acc[mt][nt][1] + b1, 0.f));
            __half2 h1 = __floats2half2_rn(fmaxf(acc[mt][nt][2] + b0, 0.f),
                                           fmaxf(acc[mt][nt][3] + b1, 0.f));
            *(uint32_t*)&out[(size_t)row * 512 + col] = h2u(h0);
            *(uint32_t*)&out[(size_t)(row + 8) * 512 + col] = h2u(h1);
        }
    }
}

// expand (transposed GEMM): Z[b][r][d][j] = (WT[r] @ X^T)[d][node]
__global__ void __launch_bounds__(128, 2) k_expand(const __half* __restrict__ X,
                                                   const __half* __restrict__ WT,
                                                   __half* __restrict__ Z) {
    extern __shared__ char smraw[];
    __half* sm = (__half*)smraw;
    const int bx = blockIdx.x, by = blockIdx.y;
    const int r = bx >> 2, d0 = (bx & 3) * 128;
    float acc[4][8][4];
    zero_acc(acc);

    LinAddr f{WT + (size_t)r * 262144u + (size_t)d0 * 512,
              X + (size_t)by * 128 * 512, 512, 512};
    gemm_main(f, 8, sm, acc);

    const int tid = threadIdx.x, lane = tid & 31, wid = tid >> 5;
    const int gid = lane >> 2, tig = lane & 3;
    const int wm = (wid >> 1) * 64, wn = (wid & 1) * 64;
#pragma unroll
    for (int mt = 0; mt < 4; mt++) {
        int d = d0 + wm + mt * 16 + gid;
#pragma unroll
        for (int nt = 0; nt < 8; nt++) {
            int m = by * 128 + wn + nt * 8 + 2 * tig;   // global node
            int b = m >> 8, j = m & 255;
            size_t zb = ((size_t)b * 7 + r) * 512u;
            __half2 h0 = __floats2half2_rn(acc[mt][nt][0], acc[mt][nt][1]);
            __half2 h1 = __floats2half2_rn(acc[mt][nt][2], acc[mt][nt][3]);
            *(uint32_t*)&Z[(zb + d) * 256u + j] = h2u(h0);
            *(uint32_t*)&Z[(zb + d + 8) * 256u + j] = h2u(h1);
        }
    }
}

// agg: out[b,i,d] = relu(sum_{r=0..6,j} EH[b,r,i,j] * Z[b,r,d,j] + bias[d])
template <bool HALF_OUT>
__global__ void __launch_bounds__(128, 2) k_agg(const __half* __restrict__ EH,
                                                const __half* __restrict__ Z,
                                                const float* __restrict__ bias,
                                                void* __restrict__ outv) {
    extern __shared__ char smraw[];
    __half* sm = (__half*)smraw;
    const int bx = blockIdx.x, by = blockIdx.y, b = blockIdx.z;
    float acc[4][8][4];
    zero_acc(acc);

    AggAddr f{EH + (size_t)b * 458752u + (size_t)(by * 128) * 256u,
              Z + (size_t)b * 917504u + (size_t)(bx * 128) * 256u, 256, 256};
    gemm_main(f, 28, sm, acc);

    const int tid = threadIdx.x, lane = tid & 31, wid = tid >> 5;
    const int gid = lane >> 2, tig = lane & 3;
    const int wm = (wid >> 1) * 64, wn = (wid & 1) * 64;
#pragma unroll
    for (int mt = 0; mt < 4; mt++) {
        int i = by * 128 + wm + mt * 16 + gid;
#pragma unroll
        for (int nt = 0; nt < 8; nt++) {
            int d = bx * 128 + wn + nt * 8 + 2 * tig;
            float b0 = bias[d], b1 = bias[d + 1];
            float r0 = fmaxf(acc[mt][nt][0] + b0, 0.f);
            float r1 = fmaxf(acc[mt][nt][1] + b1, 0.f);
            float r2 = fmaxf(acc[mt][nt][2] + b0, 0.f);
            float r3 = fmaxf(acc[mt][nt][3] + b1, 0.f);
            size_t o0 = ((size_t)b * 256 + i) * 512 + d;
            size_t o1 = ((size_t)b * 256 + i + 8) * 512 + d;
            if (HALF_OUT) {
                __half* out = (__half*)outv;
                *(uint32_t*)&out[o0] = h2u(__floats2half2_rn(r0, r1));
                *(uint32_t*)&out[o1] = h2u(__floats2half2_rn(r2, r3));
            } else {
                float* out = (float*)outv;
                *(float2*)&out[o0] = make_float2(r0, r1);
                *(float2*)&out[o1] = make_float2(r2, r3);
            }
        }
    }
}

// ---- conversion / transpose pre-kernels ------------------------------------

__global__ void k_cvt8(const float* __restrict__ src, __half* __restrict__ dst,
                       int n8) {
    int i = blockIdx.x * blockDim.x + threadIdx.x;
    if (i < n8) {
        const float4* s4 = (const float4*)src;
        float4 v0 = s4[2 * i], v1 = s4[2 * i + 1];
        uint4 o;
        o.x = h2u(__floats2half2_rn(v0.x, v0.y));
        o.y = h2u(__floats2half2_rn(v0.z, v0.w));
        o.z = h2u(__floats2half2_rn(v1.x, v1.y));
        o.w = h2u(__floats2half2_rn(v1.z, v1.w));
        ((uint4*)dst)[i] = o;
    }
}

// E fp32 [b][6][i][j] -> fp16 [b][7][i][j], slot 6 = identity
__global__ void k_cvtE(const float* __restrict__ E, __half* __restrict__ EH) {
    int b = blockIdx.z, r = blockIdx.y;
    int g = blockIdx.x * blockDim.x + threadIdx.x;   // 0..16383
    int i = g >> 6, j0 = (g & 63) * 4;
    uint2 o;
    if (r < 6) {
        float4 v = *(const float4*)&E[(((size_t)b * 6 + r) * 256 + i) * 256 + j0];
        o.x = h2u(__floats2half2_rn(v.x, v.y));
        o.y = h2u(__floats2half2_rn(v.z, v.w));
    } else {
        o.x = h2u(__floats2half2_rn(j0 == i ? 1.f : 0.f, j0 + 1 == i ? 1.f : 0.f));
        o.y = h2u(__floats2half2_rn(j0 + 2 == i ? 1.f : 0.f, j0 + 3 == i ? 1.f : 0.f));
    }
    *(uint2*)&EH[(((size_t)b * 7 + r) * 256 + i) * 256 + j0] = o;
}

// transpose + convert: src fp32 [R][C] -> dst fp16 [C][R]
__global__ void k_tcvt(const float* __restrict__ src, __half* __restrict__ dst,
                       int R, int C) {
    __shared__ float t[32][33];
    int bx = blockIdx.x * 32, by = blockIdx.y * 32;
    int x = threadIdx.x, y = threadIdx.y;
#pragma unroll
    for (int j = 0; j < 32; j += 8)
        t[y + j][x] = src[(size_t)(by + y + j) * C + bx + x];
    __syncthreads();
#pragma unroll
    for (int j = 0; j < 32; j += 8)
        dst[(size_t)(bx + y + j) * R + by + x] = __float2half_rn(t[x][y + j]);
}

// ---------------------------------------------------------------------------

extern "C" void kernel_launch(void* const* d_in, const int* in_sizes, int n_in,
                              void* d_out, int out_size) {
    const float* attn = (const float*)d_in[0];
    const float* E    = (const float*)d_in[1];
    const float* Wemb = (const float*)d_in[2];
    const float* bemb = (const float*)d_in[3];
    const float* Wr0  = (const float*)d_in[4];
    const float* Wl0  = (const float*)d_in[5];
    const float* b0   = (const float*)d_in[6];
    const float* Wr1  = (const float*)d_in[7];
    const float* Wl1  = (const float*)d_in[8];
    const float* b1   = (const float*)d_in[9];
    float* out = (float*)d_out;

    __half *attnH, *EH, *WembT, *WT, *X0, *X1, *Z;
    cudaGetSymbolAddress((void**)&attnH, g_attnH);
    cudaGetSymbolAddress((void**)&EH, g_EH);
    cudaGetSymbolAddress((void**)&WembT, g_WembT);
    cudaGetSymbolAddress((void**)&WT, g_WT);
    cudaGetSymbolAddress((void**)&X0, g_X0);
    cudaGetSymbolAddress((void**)&X1, g_X1);
    cudaGetSymbolAddress((void**)&Z, g_Z);
    __half* WT0 = WT;
    __half* WT1 = WT + 7u * 262144u;

    cudaFuncSetAttribute(k_embed, cudaFuncAttributeMaxDynamicSharedMemorySize, SMEM_BYTES);
    cudaFuncSetAttribute(k_expand, cudaFuncAttributeMaxDynamicSharedMemorySize, SMEM_BYTES);
    cudaFuncSetAttribute(k_agg<true>, cudaFuncAttributeMaxDynamicSharedMemorySize, SMEM_BYTES);
    cudaFuncSetAttribute(k_agg<false>, cudaFuncAttributeMaxDynamicSharedMemorySize, SMEM_BYTES);

    // conversions
    k_cvt8<<<32768, 256>>>(attn, attnH, 32768 * 2048 / 8);
    k_cvtE<<<dim3(64, 7, 128), 256>>>(E, EH);
    dim3 tt(32, 8);
    k_tcvt<<<dim3(16, 64), tt>>>(Wemb, WembT, 2048, 512);
    for (int r = 0; r < 7; r++) {
        k_tcvt<<<dim3(16, 16), tt>>>(r < 6 ? Wr0 + (size_t)r * 262144 : Wl0,
                                     WT0 + (size_t)r * 262144, 512, 512);
        k_tcvt<<<dim3(16, 16), tt>>>(r < 6 ? Wr1 + (size_t)r * 262144 : Wl1,
                                     WT1 + (size_t)r * 262144, 512, 512);
    }

    k_embed<<<dim3(4, 256), 128, SMEM_BYTES>>>(attnH, WembT, bemb, X0);

    k_expand<<<dim3(28, 256), 128, SMEM_BYTES>>>(X0, WT0, Z);
    k_agg<true><<<dim3(4, 2, 128), 128, SMEM_BYTES>>>(EH, Z, b0, X1);

    k_expand<<<dim3(28, 256), 128, SMEM_BYTES>>>(X1, WT1, Z);
    k_agg<false><<<dim3(4, 2, 128), 128, SMEM_BYTES>>>(EH, Z, b1, out);
}

// round 8
// speedup vs baseline: 6.5899x; 1.0252x over previous
#include <cuda_runtime.h>
#include <cuda_fp16.h>
#include <cstdint>

// ---------------------------------------------------------------------------
// RGCNEncoder via mma.sync fp16 tensor cores (m16n8k16, fp32 accumulate),
// ldmatrix fragment loads, BK=64 K-chunks, 3-stage cp.async pipeline.
// B=128, R=6, N=256, D_IN=2048, D_H=512
//
//   x0 = relu(attn @ W_embed + b_embed)
//   layer l: Z[b,r] = x[b] @ W_rel_l[r] (r<6), Z6[b] = x[b] @ W_loop_l
//            out[b] = relu(sum_{r<6} E[b,r] @ Z[b,r] + Z6[b] + bias)
//
// CTA tile 128x128, 4 warps x (64x64). Operands K-contiguous fp16.
// Z[b][r][d][j] for r<6 (agg's B layout); self-loop slice Z6 stored [n][d]
// (expand swaps operands for r==6) so agg's epilogue add is coalesced.
// ---------------------------------------------------------------------------

static __device__ __half g_attnH[32768u * 2048u];
static __device__ __half g_EH[128u * 6u * 256u * 256u];
static __device__ __half g_WembT[512u * 2048u];           // [h][din]
static __device__ __half g_WT[2][7u * 512u * 512u];       // [r][dout][din]
static __device__ __half g_X0[32768u * 512u];
static __device__ __half g_X1[32768u * 512u];
static __device__ __half g_Z[128u * 7u * 512u * 256u];    // slot6 = [n][d]

#define BK 64
#define RSTR 72   // BK + 8 pad (halves): 144B row stride, conflict-free ldmatrix

static constexpr int AS_H = 128 * RSTR;                 // 9216 halves / operand
static constexpr int STAGE_H = 2 * AS_H;                // 18432
static constexpr uint32_t AS_BYTES = AS_H * 2;          // 18432
static constexpr uint32_t STAGE_BYTES = STAGE_H * 2;    // 36864
static constexpr int SMEM_BYTES = 3 * STAGE_BYTES;      // 110592

// ---- low-level helpers -----------------------------------------------------

__device__ __forceinline__ uint32_t smem_u32(const void* p) {
    uint32_t a;
    asm("{ .reg .u64 t; cvta.to.shared.u64 t, %1; cvt.u32.u64 %0, t; }"
        : "=r"(a) : "l"(p));
    return a;
}
__device__ __forceinline__ void cp_async16(uint32_t dst, const void* src) {
    asm volatile("cp.async.cg.shared.global [%0], [%1], 16;" ::"r"(dst), "l"(src));
}
__device__ __forceinline__ void cp_commit() {
    asm volatile("cp.async.commit_group;" ::: "memory");
}
template <int N>
__device__ __forceinline__ void cp_wait() {
    asm volatile("cp.async.wait_group %0;" ::"n"(N) : "memory");
}
__device__ __forceinline__ uint32_t h2u(__half2 h) {
    return *reinterpret_cast<uint32_t*>(&h);
}
__device__ __forceinline__ void ldm_x4(uint32_t& r0, uint32_t& r1, uint32_t& r2,
                                       uint32_t& r3, uint32_t addr) {
    asm volatile("ldmatrix.sync.aligned.m8n8.x4.shared.b16 {%0,%1,%2,%3}, [%4];"
                 : "=r"(r0), "=r"(r1), "=r"(r2), "=r"(r3) : "r"(addr));
}
__device__ __forceinline__ void mma16(float* c, const uint32_t* a, const uint32_t* b) {
    asm volatile(
        "mma.sync.aligned.m16n8k16.row.col.f32.f16.f16.f32 "
        "{%0,%1,%2,%3}, {%4,%5,%6,%7}, {%8,%9}, {%0,%1,%2,%3};"
        : "+f"(c[0]), "+f"(c[1]), "+f"(c[2]), "+f"(c[3])
        : "r"(a[0]), "r"(a[1]), "r"(a[2]), "r"(a[3]), "r"(b[0]), "r"(b[1]));
}

// 128 rows x 64 halves (128B/row) tile -> padded smem, 128 threads
__device__ __forceinline__ void ld_tile(uint32_t dst, const __half* __restrict__ src,
                                        int ldk, int tid) {
#pragma unroll
    for (int i = 0; i < 8; i++) {
        int idx = tid + i * 128;
        int row = idx >> 3, seg = idx & 7;
        cp_async16(dst + (uint32_t)(row * (RSTR * 2) + seg * 16),
                   src + (size_t)row * ldk + seg * 8);
    }
}

// ---- shared mainloop -------------------------------------------------------

template <class F>
__device__ __forceinline__ void gemm_main(const F& f, int nc, __half* sm,
                                          float acc[4][8][4]) {
    const int tid = threadIdx.x;
    const uint32_t sbase = smem_u32(sm);
    const int lane = tid & 31, wid = tid >> 5;
    const int wm = (wid >> 1) * 64, wn = (wid & 1) * 64;

    const int l7 = lane & 7, lb3 = (lane >> 3) & 1, lb4 = lane >> 4;
    const uint32_t aOff = (uint32_t)((wm + l7 + lb3 * 8) * RSTR + lb4 * 8) * 2;
    const uint32_t bOff = AS_BYTES +
        (uint32_t)((wn + l7 + lb4 * 8) * RSTR + lb3 * 8) * 2;

#pragma unroll
    for (int p = 0; p < 3; p++) {
        if (p < nc) {
            ld_tile(sbase + p * STAGE_BYTES, f.a(p), f.lda, tid);
            ld_tile(sbase + p * STAGE_BYTES + AS_BYTES, f.b(p), f.ldb, tid);
        }
        cp_commit();
    }

    int stage = 0;
    for (int c = 0; c < nc; c++) {
        cp_wait<2>();
        __syncthreads();
        const uint32_t abase = sbase + stage * STAGE_BYTES + aOff;
        const uint32_t bbase = sbase + stage * STAGE_BYTES + bOff;
#pragma unroll
        for (int kk = 0; kk < BK; kk += 16) {
            uint32_t a[4][4], b[8][2];
#pragma unroll
            for (int mt = 0; mt < 4; mt++)
                ldm_x4(a[mt][0], a[mt][1], a[mt][2], a[mt][3],
                       abase + (uint32_t)(mt * 16 * RSTR + kk) * 2);
#pragma unroll
            for (int p = 0; p < 4; p++)
                ldm_x4(b[2 * p][0], b[2 * p][1], b[2 * p + 1][0], b[2 * p + 1][1],
                       bbase + (uint32_t)(p * 16 * RSTR + kk) * 2);
#pragma unroll
            for (int mt = 0; mt < 4; mt++)
#pragma unroll
                for (int nt = 0; nt < 8; nt++) mma16(acc[mt][nt], a[mt], b[nt]);
        }
        __syncthreads();
        if (c + 3 < nc) {
            ld_tile(sbase + stage * STAGE_BYTES, f.a(c + 3), f.lda, tid);
            ld_tile(sbase + stage * STAGE_BYTES + AS_BYTES, f.b(c + 3), f.ldb, tid);
        }
        cp_commit();
        stage = (stage == 2) ? 0 : stage + 1;
    }
}

__device__ __forceinline__ void zero_acc(float acc[4][8][4]) {
#pragma unroll
    for (int i = 0; i < 4; i++)
#pragma unroll
        for (int j = 0; j < 8; j++)
#pragma unroll
            for (int k = 0; k < 4; k++) acc[i][j][k] = 0.f;
}

// ---- address functors ------------------------------------------------------

struct LinAddr {
    const __half *A, *B;
    int lda, ldb;
    __device__ const __half* a(int c) const { return A + c * BK; }
    __device__ const __half* b(int c) const { return B + c * BK; }
};
struct AggAddr {
    const __half *Eb, *Zb;
    int lda, ldb;
    __device__ const __half* a(int c) const {
        return Eb + (size_t)(c >> 2) * 65536u + (c & 3) * BK;
    }
    __device__ const __half* b(int c) const {
        return Zb + (size_t)(c >> 2) * 131072u + (c & 3) * BK;
    }
};

// ---- kernels ---------------------------------------------------------------

// embed: X0[node][h] = relu(attnH @ WembT^T + bias), fp16 out
__global__ void __launch_bounds__(128, 2) k_embed(const __half* __restrict__ attn,
                                                  const __half* __restrict__ WT,
                                                  const float* __restrict__ bias,
                                                  __half* __restrict__ out) {
    extern __shared__ char smraw[];
    __half* sm = (__half*)smraw;
    const int bx = blockIdx.x, by = blockIdx.y;
    float acc[4][8][4];
    zero_acc(acc);

    LinAddr f{attn + (size_t)by * 128 * 2048, WT + (size_t)bx * 128 * 2048,
              2048, 2048};
    gemm_main(f, 32, sm, acc);

    const int tid = threadIdx.x, lane = tid & 31, wid = tid >> 5;
    const int gid = lane >> 2, tig = lane & 3;
    const int wm = (wid >> 1) * 64, wn = (wid & 1) * 64;
#pragma unroll
    for (int mt = 0; mt < 4; mt++) {
        int row = by * 128 + wm + mt * 16 + gid;
#pragma unroll
        for (int nt = 0; nt < 8; nt++) {
            int col = bx * 128 + wn + nt * 8 + 2 * tig;
            float b0 = bias[col], b1 = bias[col + 1];
            __half2 h0 = __floats2half2_rn(fmaxf(acc[mt][nt][0] + b0, 0.f),
                                           fmaxf(acc[mt][nt][1] + b1, 0.f));
            __half2 h1 = __floats2half2_rn(fmaxf(acc[mt][nt][2] + b0, 0.f),
                                           fmaxf(acc[mt][nt][3] + b1, 0.f));
            *(uint32_t*)&out[(size_t)row * 512 + col] = h2u(h0);
            *(uint32_t*)&out[(size_t)(row + 8) * 512 + col] = h2u(h1);
        }
    }
}

// expand:
//   r<6 : Z[b][r][d][j] = (WT[r] @ X^T)[d][node]   (transposed GEMM)
//   r==6: Z6[b][n][d]   = (X @ WT6^T)[node][d]     (natural GEMM, coalesced)
__global__ void __launch_bounds__(128, 2) k_expand(const __half* __restrict__ X,
                                                   const __half* __restrict__ WT,
                                                   __half* __restrict__ Z) {
    extern __shared__ char smraw[];
    __half* sm = (__half*)smraw;
    const int bx = blockIdx.x, by = blockIdx.y;
    const int r = bx >> 2, d0 = (bx & 3) * 128;
    float acc[4][8][4];
    zero_acc(acc);

    const __half* Xp = X + (size_t)by * 128 * 512;
    const __half* Wp = WT + (size_t)r * 262144u + (size_t)d0 * 512;
    const bool loop_rel = (r == 6);
    LinAddr f = loop_rel ? LinAddr{Xp, Wp, 512, 512} : LinAddr{Wp, Xp, 512, 512};
    gemm_main(f, 8, sm, acc);

    const int tid = threadIdx.x, lane = tid & 31, wid = tid >> 5;
    const int gid = lane >> 2, tig = lane & 3;
    const int wm = (wid >> 1) * 64, wn = (wid & 1) * 64;
    if (!loop_rel) {
#pragma unroll
        for (int mt = 0; mt < 4; mt++) {
            int d = d0 + wm + mt * 16 + gid;
#pragma unroll
            for (int nt = 0; nt < 8; nt++) {
                int m = by * 128 + wn + nt * 8 + 2 * tig;   // global node
                int b = m >> 8, j = m & 255;
                size_t zb = ((size_t)b * 7 + r) * 512u;
                __half2 h0 = __floats2half2_rn(acc[mt][nt][0], acc[mt][nt][1]);
                __half2 h1 = __floats2half2_rn(acc[mt][nt][2], acc[mt][nt][3]);
                *(uint32_t*)&Z[(zb + d) * 256u + j] = h2u(h0);
                *(uint32_t*)&Z[(zb + d + 8) * 256u + j] = h2u(h1);
            }
        }
    } else {
#pragma unroll
        for (int mt = 0; mt < 4; mt++) {
            int m = by * 128 + wm + mt * 16 + gid;          // global node
            int b = m >> 8, n = m & 255;
            size_t z6 = ((size_t)b * 7 + 6) * 131072u;
#pragma unroll
            for (int nt = 0; nt < 8; nt++) {
                int d = d0 + wn + nt * 8 + 2 * tig;
                __half2 h0 = __floats2half2_rn(acc[mt][nt][0], acc[mt][nt][1]);
                __half2 h1 = __floats2half2_rn(acc[mt][nt][2], acc[mt][nt][3]);
                *(uint32_t*)&Z[z6 + (size_t)n * 512 + d] = h2u(h0);
                *(uint32_t*)&Z[z6 + (size_t)(n + 8) * 512 + d] = h2u(h1);
            }
        }
    }
}

// agg: out[b,i,d] = relu(sum_{r<6,j} EH[b,r,i,j]*Z[b,r,d,j] + Z6[b,i,d] + bias[d])
template <bool HALF_OUT>
__global__ void __launch_bounds__(128, 2) k_agg(const __half* __restrict__ EH,
                                                const __half* __restrict__ Z,
                                                const float* __restrict__ bias,
                                                void* __restrict__ outv) {
    extern __shared__ char smraw[];
    __half* sm = (__half*)smraw;
    const int bx = blockIdx.x, by = blockIdx.y, b = blockIdx.z;
    float acc[4][8][4];
    zero_acc(acc);

    AggAddr f{EH + (size_t)b * 393216u + (size_t)(by * 128) * 256u,
              Z + (size_t)b * 917504u + (size_t)(bx * 128) * 256u, 256, 256};
    gemm_main(f, 24, sm, acc);

    const __half* Z6 = Z + (size_t)b * 917504u + 6u * 131072u;   // [n][d]
    const int tid = threadIdx.x, lane = tid & 31, wid = tid >> 5;
    const int gid = lane >> 2, tig = lane & 3;
    const int wm = (wid >> 1) * 64, wn = (wid & 1) * 64;
#pragma unroll
    for (int mt = 0; mt < 4; mt++) {
        int i = by * 128 + wm + mt * 16 + gid;
#pragma unroll
        for (int nt = 0; nt < 8; nt++) {
            int d = bx * 128 + wn + nt * 8 + 2 * tig;
            float b0 = bias[d], b1 = bias[d + 1];
            __half2 s0 = *(const __half2*)&Z6[(size_t)i * 512 + d];
            __half2 s1 = *(const __half2*)&Z6[(size_t)(i + 8) * 512 + d];
            float2 f0 = __half22float2(s0), f1 = __half22float2(s1);
            float r0 = fmaxf(acc[mt][nt][0] + f0.x + b0, 0.f);
            float r1 = fmaxf(acc[mt][nt][1] + f0.y + b1, 0.f);
            float r2 = fmaxf(acc[mt][nt][2] + f1.x + b0, 0.f);
            float r3 = fmaxf(acc[mt][nt][3] + f1.y + b1, 0.f);
            size_t o0 = ((size_t)b * 256 + i) * 512 + d;
            size_t o1 = ((size_t)b * 256 + i + 8) * 512 + d;
            if (HALF_OUT) {
                __half* out = (__half*)outv;
                *(uint32_t*)&out[o0] = h2u(__floats2half2_rn(r0, r1));
                *(uint32_t*)&out[o1] = h2u(__floats2half2_rn(r2, r3));
            } else {
                float* out = (float*)outv;
                *(float2*)&out[o0] = make_float2(r0, r1);
                *(float2*)&out[o1] = make_float2(r2, r3);
            }
        }
    }
}

// ---- conversion / transpose pre-kernels ------------------------------------

__global__ void k_cvt8(const float* __restrict__ src, __half* __restrict__ dst,
                       int n8) {
    int i = blockIdx.x * blockDim.x + threadIdx.x;
    if (i < n8) {
        const float4* s4 = (const float4*)src;
        float4 v0 = s4[2 * i], v1 = s4[2 * i + 1];
        uint4 o;
        o.x = h2u(__floats2half2_rn(v0.x, v0.y));
        o.y = h2u(__floats2half2_rn(v0.z, v0.w));
        o.z = h2u(__floats2half2_rn(v1.x, v1.y));
        o.w = h2u(__floats2half2_rn(v1.z, v1.w));
        ((uint4*)dst)[i] = o;
    }
}

// E fp32 [b][6][i][j] -> fp16 [b][6][i][j]
__global__ void k_cvtE(const float* __restrict__ E, __half* __restrict__ EH) {
    size_t i = (size_t)blockIdx.x * blockDim.x + threadIdx.x;  // float4 index
    const float4* s4 = (const float4*)E;
    float4 v = s4[i];
    uint2 o;
    o.x = h2u(__floats2half2_rn(v.x, v.y));
    o.y = h2u(__floats2half2_rn(v.z, v.w));
    ((uint2*)EH)[i] = o;
}

// batched transpose+convert of ALL weights in one launch.
// blocks 0..1023: Wemb (2048x512 -> WembT 512x2048), 16 x-tiles, 64 y-tiles
// blocks 1024+ : 14 mats of 512x512 (m = idx>>8; tile = idx&255)
__global__ void k_tcvt_all(const float* __restrict__ Wemb,
                           const float* __restrict__ Wr0,
                           const float* __restrict__ Wl0,
                           const float* __restrict__ Wr1,
                           const float* __restrict__ Wl1,
                           __half* __restrict__ WembT,
                           __half* __restrict__ WT) {
    __shared__ float t[32][33];
    int bid = blockIdx.x;
    const float* src;
    __half* dst;
    int R, C, tx, ty;
    if (bid < 1024) {
        src = Wemb; dst = WembT; R = 2048; C = 512;
        tx = bid & 15; ty = bid >> 4;
    } else {
        int idx = bid - 1024;
        int m = idx >> 8, tile = idx & 255;
        int layer = m / 7, r = m % 7;
        src = (r < 6) ? (layer ? Wr1 : Wr0) + (size_t)r * 262144u
                      : (layer ? Wl1 : Wl0);
        dst = WT + (size_t)m * 262144u;
        R = 512; C = 512;
        tx = tile & 15; ty = tile >> 4;
    }
    int bx = tx * 32, by = ty * 32;
    int x = threadIdx.x, y = threadIdx.y;
#pragma unroll
    for (int j = 0; j < 32; j += 8)
        t[y + j][x] = src[(size_t)(by + y + j) * C + bx + x];
    __syncthreads();
#pragma unroll
    for (int j = 0; j < 32; j += 8)
        dst[(size_t)(bx + y + j) * R + by + x] = __float2half_rn(t[x][y + j]);
}

// ---------------------------------------------------------------------------

extern "C" void kernel_launch(void* const* d_in, const int* in_sizes, int n_in,
                              void* d_out, int out_size) {
    const float* attn = (const float*)d_in[0];
    const float* E    = (const float*)d_in[1];
    const float* Wemb = (const float*)d_in[2];
    const float* bemb = (const float*)d_in[3];
    const float* Wr0  = (const float*)d_in[4];
    const float* Wl0  = (const float*)d_in[5];
    const float* b0   = (const float*)d_in[6];
    const float* Wr1  = (const float*)d_in[7];
    const float* Wl1  = (const float*)d_in[8];
    const float* b1   = (const float*)d_in[9];
    float* out = (float*)d_out;

    __half *attnH, *EH, *WembT, *WT, *X0, *X1, *Z;
    cudaGetSymbolAddress((void**)&attnH, g_attnH);
    cudaGetSymbolAddress((void**)&EH, g_EH);
    cudaGetSymbolAddress((void**)&WembT, g_WembT);
    cudaGetSymbolAddress((void**)&WT, g_WT);
    cudaGetSymbolAddress((void**)&X0, g_X0);
    cudaGetSymbolAddress((void**)&X1, g_X1);
    cudaGetSymbolAddress((void**)&Z, g_Z);
    __half* WT0 = WT;
    __half* WT1 = WT + 7u * 262144u;

    cudaFuncSetAttribute(k_embed, cudaFuncAttributeMaxDynamicSharedMemorySize, SMEM_BYTES);
    cudaFuncSetAttribute(k_expand, cudaFuncAttributeMaxDynamicSharedMemorySize, SMEM_BYTES);
    cudaFuncSetAttribute(k_agg<true>, cudaFuncAttributeMaxDynamicSharedMemorySize, SMEM_BYTES);
    cudaFuncSetAttribute(k_agg<false>, cudaFuncAttributeMaxDynamicSharedMemorySize, SMEM_BYTES);

    // launch order keeps the 6th launch = first k_agg (ncu -s 5 -c 1 target)
    k_tcvt_all<<<1024 + 14 * 256, dim3(32, 8)>>>(Wemb, Wr0, Wl0, Wr1, Wl1,
                                                 WembT, WT);
    k_cvt8<<<32768, 256>>>(attn, attnH, 32768 * 2048 / 8);
    k_cvtE<<<128u * 6u * 256u * 256u / 4u / 256u, 256>>>(E, EH);

    k_embed<<<dim3(4, 256), 128, SMEM_BYTES>>>(attnH, WembT, bemb, X0);

    k_expand<<<dim3(28, 256), 128, SMEM_BYTES>>>(X0, WT0, Z);
    k_agg<true><<<dim3(4, 2, 128), 128, SMEM_BYTES>>>(EH, Z, b0, X1);

    k_expand<<<dim3(28, 256), 128, SMEM_BYTES>>>(X1, WT1, Z);
    k_agg<false><<<dim3(4, 2, 128), 128, SMEM_BYTES>>>(EH, Z, b1, out);
}

// round 9
// speedup vs baseline: 6.8521x; 1.0398x over previous
#include <cuda_runtime.h>
#include <cuda_fp16.h>
#include <cstdint>

// ---------------------------------------------------------------------------
// RGCNEncoder via mma.sync fp16 tensor cores (m16n8k16, fp32 accumulate),
// ldmatrix fragment loads, BK=64 K-chunks, 3-stage cp.async pipeline with a
// SINGLE __syncthreads per chunk (loads issued before compute).
// B=128, R=6, N=256, D_IN=2048, D_H=512
//
//   x0 = relu(attn @ W_embed + b_embed)
//   layer l: Z[b,r] = x[b] @ W_rel_l[r] (r<6), Z6[b] = x[b] @ W_loop_l
//            out[b] = relu(sum_{r<6} E[b,r] @ Z[b,r] + Z6[b] + bias)
//
// CTA tile 128x128, 4 warps x (64x64). Operands K-contiguous fp16.
// Z[b][r][d][j] for r<6 (agg's B layout); self-loop slice Z6 stored [n][d]
// (expand swaps operands for r==6) so agg's epilogue add is coalesced.
// ---------------------------------------------------------------------------

static __device__ __half g_attnH[32768u * 2048u];
static __device__ __half g_EH[128u * 6u * 256u * 256u];
static __device__ __half g_WembT[512u * 2048u];           // [h][din]
static __device__ __half g_WT[2][7u * 512u * 512u];       // [r][dout][din]
static __device__ __half g_X0[32768u * 512u];
static __device__ __half g_X1[32768u * 512u];
static __device__ __half g_Z[128u * 7u * 512u * 256u];    // slot6 = [n][d]

#define BK 64
#define RSTR 72   // BK + 8 pad (halves): 144B row stride, conflict-free ldmatrix

static constexpr int AS_H = 128 * RSTR;                 // 9216 halves / operand
static constexpr int STAGE_H = 2 * AS_H;                // 18432
static constexpr uint32_t AS_BYTES = AS_H * 2;          // 18432
static constexpr uint32_t STAGE_BYTES = STAGE_H * 2;    // 36864
static constexpr int SMEM_BYTES = 3 * STAGE_BYTES;      // 110592

// ---- low-level helpers -----------------------------------------------------

__device__ __forceinline__ uint32_t smem_u32(const void* p) {
    uint32_t a;
    asm("{ .reg .u64 t; cvta.to.shared.u64 t, %1; cvt.u32.u64 %0, t; }"
        : "=r"(a) : "l"(p));
    return a;
}
__device__ __forceinline__ void cp_async16(uint32_t dst, const void* src) {
    asm volatile("cp.async.cg.shared.global [%0], [%1], 16;" ::"r"(dst), "l"(src));
}
__device__ __forceinline__ void cp_commit() {
    asm volatile("cp.async.commit_group;" ::: "memory");
}
template <int N>
__device__ __forceinline__ void cp_wait() {
    asm volatile("cp.async.wait_group %0;" ::"n"(N) : "memory");
}
__device__ __forceinline__ uint32_t h2u(__half2 h) {
    return *reinterpret_cast<uint32_t*>(&h);
}
__device__ __forceinline__ void ldm_x4(uint32_t& r0, uint32_t& r1, uint32_t& r2,
                                       uint32_t& r3, uint32_t addr) {
    asm volatile("ldmatrix.sync.aligned.m8n8.x4.shared.b16 {%0,%1,%2,%3}, [%4];"
                 : "=r"(r0), "=r"(r1), "=r"(r2), "=r"(r3) : "r"(addr));
}
__device__ __forceinline__ void mma16(float* c, const uint32_t* a, const uint32_t* b) {
    asm volatile(
        "mma.sync.aligned.m16n8k16.row.col.f32.f16.f16.f32 "
        "{%0,%1,%2,%3}, {%4,%5,%6,%7}, {%8,%9}, {%0,%1,%2,%3};"
        : "+f"(c[0]), "+f"(c[1]), "+f"(c[2]), "+f"(c[3])
        : "r"(a[0]), "r"(a[1]), "r"(a[2]), "r"(a[3]), "r"(b[0]), "r"(b[1]));
}

// 128 rows x 64 halves (128B/row) tile -> padded smem, 128 threads
__device__ __forceinline__ void ld_tile(uint32_t dst, const __half* __restrict__ src,
                                        int ldk, int tid) {
#pragma unroll
    for (int i = 0; i < 8; i++) {
        int idx = tid + i * 128;
        int row = idx >> 3, seg = idx & 7;
        cp_async16(dst + (uint32_t)(row * (RSTR * 2) + seg * 16),
                   src + (size_t)row * ldk + seg * 8);
    }
}

// ---- shared mainloop -------------------------------------------------------
// 3-stage, single barrier per chunk. At iter c the load target stage
// (c+2)%3 == (c-1)%3 was consumed at iter c-1; the barrier at iter c proves
// every warp finished reading it (bar.sync completes prior shared accesses).

template <class F>
__device__ __forceinline__ void gemm_main(const F& f, int nc, __half* sm,
                                          float acc[4][8][4]) {
    const int tid = threadIdx.x;
    const uint32_t sbase = smem_u32(sm);
    const int lane = tid & 31, wid = tid >> 5;
    const int wm = (wid >> 1) * 64, wn = (wid & 1) * 64;

    const int l7 = lane & 7, lb3 = (lane >> 3) & 1, lb4 = lane >> 4;
    const uint32_t aOff = (uint32_t)((wm + l7 + lb3 * 8) * RSTR + lb4 * 8) * 2;
    const uint32_t bOff = AS_BYTES +
        (uint32_t)((wn + l7 + lb4 * 8) * RSTR + lb3 * 8) * 2;

    // prologue: stages 0, 1
#pragma unroll
    for (int p = 0; p < 2; p++) {
        if (p < nc) {
            ld_tile(sbase + p * STAGE_BYTES, f.a(p), f.lda, tid);
            ld_tile(sbase + p * STAGE_BYTES + AS_BYTES, f.b(p), f.ldb, tid);
        }
        cp_commit();
    }

    int stage = 0, nxt = 2;
    for (int c = 0; c < nc; c++) {
        if (c + 1 < nc) cp_wait<1>(); else cp_wait<0>();
        __syncthreads();
        // issue next-stage loads FIRST, then compute (DMA overlaps MMAs)
        if (c + 2 < nc) {
            ld_tile(sbase + nxt * STAGE_BYTES, f.a(c + 2), f.lda, tid);
            ld_tile(sbase + nxt * STAGE_BYTES + AS_BYTES, f.b(c + 2), f.ldb, tid);
            cp_commit();
        }
        const uint32_t abase = sbase + stage * STAGE_BYTES + aOff;
        const uint32_t bbase = sbase + stage * STAGE_BYTES + bOff;
#pragma unroll
        for (int kk = 0; kk < BK; kk += 16) {
            uint32_t a[4][4], b[8][2];
#pragma unroll
            for (int mt = 0; mt < 4; mt++)
                ldm_x4(a[mt][0], a[mt][1], a[mt][2], a[mt][3],
                       abase + (uint32_t)(mt * 16 * RSTR + kk) * 2);
#pragma unroll
            for (int p = 0; p < 4; p++)
                ldm_x4(b[2 * p][0], b[2 * p][1], b[2 * p + 1][0], b[2 * p + 1][1],
                       bbase + (uint32_t)(p * 16 * RSTR + kk) * 2);
#pragma unroll
            for (int mt = 0; mt < 4; mt++)
#pragma unroll
                for (int nt = 0; nt < 8; nt++) mma16(acc[mt][nt], a[mt], b[nt]);
        }
        stage = (stage == 2) ? 0 : stage + 1;
        nxt = (nxt == 2) ? 0 : nxt + 1;
    }
}

__device__ __forceinline__ void zero_acc(float acc[4][8][4]) {
#pragma unroll
    for (int i = 0; i < 4; i++)
#pragma unroll
        for (int j = 0; j < 8; j++)
#pragma unroll
            for (int k = 0; k < 4; k++) acc[i][j][k] = 0.f;
}

// ---- address functors ------------------------------------------------------

struct LinAddr {
    const __half *A, *B;
    int lda, ldb;
    __device__ const __half* a(int c) const { return A + c * BK; }
    __device__ const __half* b(int c) const { return B + c * BK; }
};
struct AggAddr {
    const __half *Eb, *Zb;
    int lda, ldb;
    __device__ const __half* a(int c) const {
        return Eb + (size_t)(c >> 2) * 65536u + (c & 3) * BK;
    }
    __device__ const __half* b(int c) const {
        return Zb + (size_t)(c >> 2) * 131072u + (c & 3) * BK;
    }
};

// ---- kernels ---------------------------------------------------------------

// embed: X0[node][h] = relu(attnH @ WembT^T + bias), fp16 out
__global__ void __launch_bounds__(128, 2) k_embed(const __half* __restrict__ attn,
                                                  const __half* __restrict__ WT,
                                                  const float* __restrict__ bias,
                                                  __half* __restrict__ out) {
    extern __shared__ char smraw[];
    __half* sm = (__half*)smraw;
    const int bx = blockIdx.x, by = blockIdx.y;
    float acc[4][8][4];
    zero_acc(acc);

    LinAddr f{attn + (size_t)by * 128 * 2048, WT + (size_t)bx * 128 * 2048,
              2048, 2048};
    gemm_main(f, 32, sm, acc);

    const int tid = threadIdx.x, lane = tid & 31, wid = tid >> 5;
    const int gid = lane >> 2, tig = lane & 3;
    const int wm = (wid >> 1) * 64, wn = (wid & 1) * 64;
#pragma unroll
    for (int mt = 0; mt < 4; mt++) {
        int row = by * 128 + wm + mt * 16 + gid;
#pragma unroll
        for (int nt = 0; nt < 8; nt++) {
            int col = bx * 128 + wn + nt * 8 + 2 * tig;
            float b0 = bias[col], b1 = bias[col + 1];
            __half2 h0 = __floats2half2_rn(fmaxf(acc[mt][nt][0] + b0, 0.f),
                                           fmaxf(acc[mt][nt][1] + b1, 0.f));
            __half2 h1 = __floats2half2_rn(fmaxf(acc[mt][nt][2] + b0, 0.f),
                                           fmaxf(acc[mt][nt][3] + b1, 0.f));
            *(uint32_t*)&out[(size_t)row * 512 + col] = h2u(h0);
            *(uint32_t*)&out[(size_t)(row + 8) * 512 + col] = h2u(h1);
        }
    }
}

// expand:
//   r<6 : Z[b][r][d][j] = (WT[r] @ X^T)[d][node]   (transposed GEMM)
//   r==6: Z6[b][n][d]   = (X @ WT6^T)[node][d]     (natural GEMM, coalesced)
__global__ void __launch_bounds__(128, 2) k_expand(const __half* __restrict__ X,
                                                   const __half* __restrict__ WT,
                                                   __half* __restrict__ Z) {
    extern __shared__ char smraw[];
    __half* sm = (__half*)smraw;
    const int bx = blockIdx.x, by = blockIdx.y;
    const int r = bx >> 2, d0 = (bx & 3) * 128;
    float acc[4][8][4];
    zero_acc(acc);

    const __half* Xp = X + (size_t)by * 128 * 512;
    const __half* Wp = WT + (size_t)r * 262144u + (size_t)d0 * 512;
    const bool loop_rel = (r == 6);
    LinAddr f = loop_rel ? LinAddr{Xp, Wp, 512, 512} : LinAddr{Wp, Xp, 512, 512};
    gemm_main(f, 8, sm, acc);

    const int tid = threadIdx.x, lane = tid & 31, wid = tid >> 5;
    const int gid = lane >> 2, tig = lane & 3;
    const int wm = (wid >> 1) * 64, wn = (wid & 1) * 64;
    if (!loop_rel) {
#pragma unroll
        for (int mt = 0; mt < 4; mt++) {
            int d = d0 + wm + mt * 16 + gid;
#pragma unroll
            for (int nt = 0; nt < 8; nt++) {
                int m = by * 128 + wn + nt * 8 + 2 * tig;   // global node
                int b = m >> 8, j = m & 255;
                size_t zb = ((size_t)b * 7 + r) * 512u;
                __half2 h0 = __floats2half2_rn(acc[mt][nt][0], acc[mt][nt][1]);
                __half2 h1 = __floats2half2_rn(acc[mt][nt][2], acc[mt][nt][3]);
                *(uint32_t*)&Z[(zb + d) * 256u + j] = h2u(h0);
                *(uint32_t*)&Z[(zb + d + 8) * 256u + j] = h2u(h1);
            }
        }
    } else {
#pragma unroll
        for (int mt = 0; mt < 4; mt++) {
            int m = by * 128 + wm + mt * 16 + gid;          // global node
            int b = m >> 8, n = m & 255;
            size_t z6 = ((size_t)b * 7 + 6) * 131072u;
#pragma unroll
            for (int nt = 0; nt < 8; nt++) {
                int d = d0 + wn + nt * 8 + 2 * tig;
                __half2 h0 = __floats2half2_rn(acc[mt][nt][0], acc[mt][nt][1]);
                __half2 h1 = __floats2half2_rn(acc[mt][nt][2], acc[mt][nt][3]);
                *(uint32_t*)&Z[z6 + (size_t)n * 512 + d] = h2u(h0);
                *(uint32_t*)&Z[z6 + (size_t)(n + 8) * 512 + d] = h2u(h1);
            }
        }
    }
}

// agg: out[b,i,d] = relu(sum_{r<6,j} EH[b,r,i,j]*Z[b,r,d,j] + Z6[b,i,d] + bias[d])
template <bool HALF_OUT>
__global__ void __launch_bounds__(128, 2) k_agg(const __half* __restrict__ EH,
                                                const __half* __restrict__ Z,
                                                const float* __restrict__ bias,
                                                void* __restrict__ outv) {
    extern __shared__ char smraw[];
    __half* sm = (__half*)smraw;
    const int bx = blockIdx.x, by = blockIdx.y, b = blockIdx.z;
    float acc[4][8][4];
    zero_acc(acc);

    AggAddr f{EH + (size_t)b * 393216u + (size_t)(by * 128) * 256u,
              Z + (size_t)b * 917504u + (size_t)(bx * 128) * 256u, 256, 256};
    gemm_main(f, 24, sm, acc);

    const __half* Z6 = Z + (size_t)b * 917504u + 6u * 131072u;   // [n][d]
    const int tid = threadIdx.x, lane = tid & 31, wid = tid >> 5;
    const int gid = lane >> 2, tig = lane & 3;
    const int wm = (wid >> 1) * 64, wn = (wid & 1) * 64;
#pragma unroll
    for (int mt = 0; mt < 4; mt++) {
        int i = by * 128 + wm + mt * 16 + gid;
#pragma unroll
        for (int nt = 0; nt < 8; nt++) {
            int d = bx * 128 + wn + nt * 8 + 2 * tig;
            float b0 = bias[d], b1 = bias[d + 1];
            __half2 s0 = *(const __half2*)&Z6[(size_t)i * 512 + d];
            __half2 s1 = *(const __half2*)&Z6[(size_t)(i + 8) * 512 + d];
            float2 f0 = __half22float2(s0), f1 = __half22float2(s1);
            float r0 = fmaxf(acc[mt][nt][0] + f0.x + b0, 0.f);
            float r1 = fmaxf(acc[mt][nt][1] + f0.y + b1, 0.f);
            float r2 = fmaxf(acc[mt][nt][2] + f1.x + b0, 0.f);
            float r3 = fmaxf(acc[mt][nt][3] + f1.y + b1, 0.f);
            size_t o0 = ((size_t)b * 256 + i) * 512 + d;
            size_t o1 = ((size_t)b * 256 + i + 8) * 512 + d;
            if (HALF_OUT) {
                __half* out = (__half*)outv;
                *(uint32_t*)&out[o0] = h2u(__floats2half2_rn(r0, r1));
                *(uint32_t*)&out[o1] = h2u(__floats2half2_rn(r2, r3));
            } else {
                float* out = (float*)outv;
                *(float2*)&out[o0] = make_float2(r0, r1);
                *(float2*)&out[o1] = make_float2(r2, r3);
            }
        }
    }
}

// ---- conversion / transpose pre-kernels ------------------------------------

__global__ void k_cvt8(const float* __restrict__ src, __half* __restrict__ dst,
                       int n8) {
    int i = blockIdx.x * blockDim.x + threadIdx.x;
    if (i < n8) {
        const float4* s4 = (const float4*)src;
        float4 v0 = s4[2 * i], v1 = s4[2 * i + 1];
        uint4 o;
        o.x = h2u(__floats2half2_rn(v0.x, v0.y));
        o.y = h2u(__floats2half2_rn(v0.z, v0.w));
        o.z = h2u(__floats2half2_rn(v1.x, v1.y));
        o.w = h2u(__floats2half2_rn(v1.z, v1.w));
        ((uint4*)dst)[i] = o;
    }
}

// E fp32 [b][6][i][j] -> fp16 [b][6][i][j]
__global__ void k_cvtE(const float* __restrict__ E, __half* __restrict__ EH) {
    size_t i = (size_t)blockIdx.x * blockDim.x + threadIdx.x;  // float4 index
    const float4* s4 = (const float4*)E;
    float4 v = s4[i];
    uint2 o;
    o.x = h2u(__floats2half2_rn(v.x, v.y));
    o.y = h2u(__floats2half2_rn(v.z, v.w));
    ((uint2*)EH)[i] = o;
}

// batched transpose+convert of ALL weights in one launch.
__global__ void k_tcvt_all(const float* __restrict__ Wemb,
                           const float* __restrict__ Wr0,
                           const float* __restrict__ Wl0,
                           const float* __restrict__ Wr1,
                           const float* __restrict__ Wl1,
                           __half* __restrict__ WembT,
                           __half* __restrict__ WT) {
    __shared__ float t[32][33];
    int bid = blockIdx.x;
    const float* src;
    __half* dst;
    int R, C, tx, ty;
    if (bid < 1024) {
        src = Wemb; dst = WembT; R = 2048; C = 512;
        tx = bid & 15; ty = bid >> 4;
    } else {
        int idx = bid - 1024;
        int m = idx >> 8, tile = idx & 255;
        int layer = m / 7, r = m % 7;
        src = (r < 6) ? (layer ? Wr1 : Wr0) + (size_t)r * 262144u
                      : (layer ? Wl1 : Wl0);
        dst = WT + (size_t)m * 262144u;
        R = 512; C = 512;
        tx = tile & 15; ty = tile >> 4;
    }
    int bx = tx * 32, by = ty * 32;
    int x = threadIdx.x, y = threadIdx.y;
#pragma unroll
    for (int j = 0; j < 32; j += 8)
        t[y + j][x] = src[(size_t)(by + y + j) * C + bx + x];
    __syncthreads();
#pragma unroll
    for (int j = 0; j < 32; j += 8)
        dst[(size_t)(bx + y + j) * R + by + x] = __float2half_rn(t[x][y + j]);
}

// ---------------------------------------------------------------------------

extern "C" void kernel_launch(void* const* d_in, const int* in_sizes, int n_in,
                              void* d_out, int out_size) {
    const float* attn = (const float*)d_in[0];
    const float* E    = (const float*)d_in[1];
    const float* Wemb = (const float*)d_in[2];
    const float* bemb = (const float*)d_in[3];
    const float* Wr0  = (const float*)d_in[4];
    const float* Wl0  = (const float*)d_in[5];
    const float* b0   = (const float*)d_in[6];
    const float* Wr1  = (const float*)d_in[7];
    const float* Wl1  = (const float*)d_in[8];
    const float* b1   = (const float*)d_in[9];
    float* out = (float*)d_out;

    __half *attnH, *EH, *WembT, *WT, *X0, *X1, *Z;
    cudaGetSymbolAddress((void**)&attnH, g_attnH);
    cudaGetSymbolAddress((void**)&EH, g_EH);
    cudaGetSymbolAddress((void**)&WembT, g_WembT);
    cudaGetSymbolAddress((void**)&WT, g_WT);
    cudaGetSymbolAddress((void**)&X0, g_X0);
    cudaGetSymbolAddress((void**)&X1, g_X1);
    cudaGetSymbolAddress((void**)&Z, g_Z);
    __half* WT0 = WT;
    __half* WT1 = WT + 7u * 262144u;

    cudaFuncSetAttribute(k_embed, cudaFuncAttributeMaxDynamicSharedMemorySize, SMEM_BYTES);
    cudaFuncSetAttribute(k_expand, cudaFuncAttributeMaxDynamicSharedMemorySize, SMEM_BYTES);
    cudaFuncSetAttribute(k_agg<true>, cudaFuncAttributeMaxDynamicSharedMemorySize, SMEM_BYTES);
    cudaFuncSetAttribute(k_agg<false>, cudaFuncAttributeMaxDynamicSharedMemorySize, SMEM_BYTES);

    k_tcvt_all<<<1024 + 14 * 256, dim3(32, 8)>>>(Wemb, Wr0, Wl0, Wr1, Wl1,
                                                 WembT, WT);
    k_cvt8<<<32768, 256>>>(attn, attnH, 32768 * 2048 / 8);
    k_cvtE<<<128u * 6u * 256u * 256u / 4u / 256u, 256>>>(E, EH);

    k_embed<<<dim3(4, 256), 128, SMEM_BYTES>>>(attnH, WembT, bemb, X0);

    k_expand<<<dim3(28, 256), 128, SMEM_BYTES>>>(X0, WT0, Z);
    k_agg<true><<<dim3(4, 2, 128), 128, SMEM_BYTES>>>(EH, Z, b0, X1);

    k_expand<<<dim3(28, 256), 128, SMEM_BYTES>>>(X1, WT1, Z);
    k_agg<false><<<dim3(4, 2, 128), 128, SMEM_BYTES>>>(EH, Z, b1, out);
}